// round 7
// baseline (speedup 1.0000x reference)
#include <cuda_runtime.h>
#include <cuda_bf16.h>
#include <cstdint>

#define BB 4
#define LL 2048
#define DD 512
#define NLAY 2
#define EDIM 1024
#define NSTATE 16
#define RRANK 32
#define KCONV 4
#define MM (BB*LL)   // 8192 tokens

// ---------------- scratch (static device allocations) ---------------------------
__device__ float g_dbc[(size_t)MM * 64];            // x-proj output (dt|B|C) fp32
__device__ float g_delta[(size_t)MM * EDIM];        // softplus(dt proj) fp32
__device__ __nv_bfloat16 g_u_bf[(size_t)MM * DD];       // normed input
__device__ __nv_bfloat16 g_xp_bf[(size_t)MM * EDIM];    // in-proj x half
__device__ __nv_bfloat16 g_z_bf[(size_t)MM * EDIM];     // in-proj z half
__device__ __nv_bfloat16 g_xc_bf[(size_t)MM * EDIM];    // conv+silu output
__device__ __nv_bfloat16 g_y_bf[(size_t)MM * EDIM];     // scan output
__device__ __nv_bfloat16 g_inw_bf[(size_t)NLAY * 2 * EDIM * DD];
__device__ __nv_bfloat16 g_outw_bf[(size_t)NLAY * DD * EDIM];
__device__ __nv_bfloat16 g_xprojw_bf[(size_t)NLAY * 64 * EDIM];

// ================= helpers ======================================================
__device__ __forceinline__ uint32_t smem_u32(const void* p) {
    uint32_t a;
    asm("{ .reg .u64 t; cvta.to.shared.u64 t, %1; cvt.u32.u64 %0, t; }"
        : "=r"(a) : "l"(p));
    return a;
}
#define SWZ(o) ((o) ^ (((o) >> 3) & 0x70))

__device__ __forceinline__ void cp16(uint32_t dst, const void* src) {
    asm volatile("cp.async.cg.shared.global [%0], [%1], 16;" :: "r"(dst), "l"(src));
}
__device__ __forceinline__ void cp_commit() {
    asm volatile("cp.async.commit_group;");
}
template<int N>
__device__ __forceinline__ void cp_wait() {
    asm volatile("cp.async.wait_group %0;" :: "n"(N));
}

__device__ __forceinline__ void ldsm_x4(uint32_t& r0, uint32_t& r1,
                                        uint32_t& r2, uint32_t& r3, uint32_t addr) {
    asm volatile("ldmatrix.sync.aligned.m8n8.x4.shared.b16 {%0,%1,%2,%3}, [%4];"
                 : "=r"(r0), "=r"(r1), "=r"(r2), "=r"(r3) : "r"(addr));
}
__device__ __forceinline__ void mma16816(float* d, const uint32_t* a, const uint32_t* b) {
    asm volatile("mma.sync.aligned.m16n8k16.row.col.f32.bf16.bf16.f32 "
                 "{%0,%1,%2,%3}, {%4,%5,%6,%7}, {%8,%9}, {%0,%1,%2,%3};"
                 : "+f"(d[0]), "+f"(d[1]), "+f"(d[2]), "+f"(d[3])
                 : "r"(a[0]), "r"(a[1]), "r"(a[2]), "r"(a[3]),
                   "r"(b[0]), "r"(b[1]));
}

// ================= bf16 HMMA GEMM: C[M,N] = A[M,K] @ B[N,K]^T ===================
// EPI 0: fp32 C store.
// EPI 1: split bf16 store: n<EDIM -> xp_bf, else -> z_bf (both [M][EDIM]).
// EPI 2: C = (C + acc) * mask[m]  (fp32 residual in-place)
template<int BN, int EPI>
__global__ __launch_bounds__(256)
void mma_gemm(const __nv_bfloat16* __restrict__ A, const __nv_bfloat16* __restrict__ Bw,
              float* __restrict__ C,
              __nv_bfloat16* __restrict__ xp_bf, __nv_bfloat16* __restrict__ z_bf,
              int M, int N, int K, int ldc, const int* __restrict__ mask) {
    constexpr int BM = 128, BK = 64;
    constexpr int NW = 4, MW = 2;            // warp grid 2 (M) x 4 (N)
    constexpr int WM = BM / MW;              // 64
    constexpr int WN = BN / NW;              // 32 or 16
    constexpr int MFRAG = WM / 16;           // 4
    constexpr int NFRAG = WN / 8;            // 4 or 2
    constexpr int ASZ = BM * 128;            // bytes per A stage
    constexpr int BSZ = BN * 128;

    extern __shared__ __align__(128) char dynsmem[];
    char* sA = dynsmem;                      // 2 stages
    char* sB = dynsmem + 2 * ASZ;

    int tid = threadIdx.x;
    int wid = tid >> 5, lane = tid & 31;
    int bm = blockIdx.y * BM, bn = blockIdx.x * BN;
    int wm = (wid / NW) * WM;
    int wn = (wid % NW) * WN;
    uint32_t sAb = smem_u32(sA), sBb = smem_u32(sB);

    // per-lane ldmatrix base offsets (within a stage, without k-step term)
    uint32_t aBase[MFRAG];
    #pragma unroll
    for (int i = 0; i < MFRAG; i++)
        aBase[i] = (uint32_t)((wm + i * 16 + (lane & 15)) * 128 + (lane >> 4) * 16);
    uint32_t bBase[NFRAG / 2];
    #pragma unroll
    for (int j = 0; j < NFRAG / 2; j++)
        bBase[j] = (uint32_t)((wn + j * 16 + (lane & 7) + ((lane >> 4) & 1) * 8) * 128
                              + ((lane >> 3) & 1) * 16);

    float acc[MFRAG][NFRAG][4];
    #pragma unroll
    for (int i = 0; i < MFRAG; i++)
        #pragma unroll
        for (int j = 0; j < NFRAG; j++)
            #pragma unroll
            for (int q = 0; q < 4; q++) acc[i][j][q] = 0.f;

    const int nk = K / BK;

#define LOAD_STAGE(kc, st) do {                                                 \
        _Pragma("unroll")                                                       \
        for (int i = 0; i < (BM * 8) / 256; i++) {                              \
            int idx = tid + i * 256;                                            \
            int r = idx >> 3, c8 = idx & 7;                                     \
            cp16(sAb + (st) * ASZ + SWZ((uint32_t)(r * 128 + c8 * 16)),         \
                 A + (size_t)(bm + r) * K + (kc) * 64 + c8 * 8);                \
        }                                                                       \
        _Pragma("unroll")                                                       \
        for (int i = 0; i < (BN * 8) / 256; i++) {                              \
            int idx = tid + i * 256;                                            \
            int r = idx >> 3, c8 = idx & 7;                                     \
            cp16(sBb + (st) * BSZ + SWZ((uint32_t)(r * 128 + c8 * 16)),         \
                 Bw + (size_t)(bn + r) * K + (kc) * 64 + c8 * 8);               \
        }                                                                       \
        cp_commit();                                                            \
    } while (0)

    LOAD_STAGE(0, 0);
    for (int kc = 0; kc < nk; kc++) {
        int st = kc & 1;
        if (kc + 1 < nk) {
            LOAD_STAGE(kc + 1, st ^ 1);
            cp_wait<1>();
        } else {
            cp_wait<0>();
        }
        __syncthreads();

        uint32_t aS = sAb + st * ASZ, bS = sBb + st * BSZ;
        #pragma unroll
        for (int ks = 0; ks < 4; ks++) {
            uint32_t af[MFRAG][4];
            #pragma unroll
            for (int i = 0; i < MFRAG; i++)
                ldsm_x4(af[i][0], af[i][1], af[i][2], af[i][3],
                        aS + SWZ(aBase[i] + ks * 32));
            uint32_t bf[NFRAG][2];
            #pragma unroll
            for (int j = 0; j < NFRAG / 2; j++) {
                uint32_t r0, r1, r2, r3;
                ldsm_x4(r0, r1, r2, r3, bS + SWZ(bBase[j] + ks * 32));
                bf[j * 2][0] = r0; bf[j * 2][1] = r1;
                bf[j * 2 + 1][0] = r2; bf[j * 2 + 1][1] = r3;
            }
            #pragma unroll
            for (int i = 0; i < MFRAG; i++)
                #pragma unroll
                for (int j = 0; j < NFRAG; j++)
                    mma16816(acc[i][j], af[i], bf[j]);
        }
        __syncthreads();
    }
#undef LOAD_STAGE

    // ---- epilogue ----
    bool isz = false;
    __nv_bfloat16* OB = nullptr;
    if (EPI == 1) { isz = (bn >= EDIM); OB = isz ? z_bf : xp_bf; }
    #pragma unroll
    for (int i = 0; i < MFRAG; i++) {
        int r0 = bm + wm + i * 16 + (lane >> 2);
        int r1 = r0 + 8;
        float mk0 = 1.f, mk1 = 1.f;
        if (EPI == 2) { mk0 = (float)mask[r0]; mk1 = (float)mask[r1]; }
        #pragma unroll
        for (int j = 0; j < NFRAG; j++) {
            int c = bn + wn + j * 8 + (lane & 3) * 2;
            if (EPI == 1) {
                int cb = c - (isz ? EDIM : 0);
                __nv_bfloat162 b0 = __floats2bfloat162_rn(acc[i][j][0], acc[i][j][1]);
                __nv_bfloat162 b1 = __floats2bfloat162_rn(acc[i][j][2], acc[i][j][3]);
                *reinterpret_cast<__nv_bfloat162*>(OB + (size_t)r0 * EDIM + cb) = b0;
                *reinterpret_cast<__nv_bfloat162*>(OB + (size_t)r1 * EDIM + cb) = b1;
            } else {
                size_t i0 = (size_t)r0 * ldc + c;
                size_t i1 = (size_t)r1 * ldc + c;
                float2 v0 = make_float2(acc[i][j][0], acc[i][j][1]);
                float2 v1 = make_float2(acc[i][j][2], acc[i][j][3]);
                if (EPI == 2) {
                    float2 o0 = *reinterpret_cast<float2*>(C + i0);
                    float2 o1 = *reinterpret_cast<float2*>(C + i1);
                    v0 = make_float2((o0.x + v0.x) * mk0, (o0.y + v0.y) * mk0);
                    v1 = make_float2((o1.x + v1.x) * mk1, (o1.y + v1.y) * mk1);
                }
                *reinterpret_cast<float2*>(C + i0) = v0;
                *reinterpret_cast<float2*>(C + i1) = v1;
            }
        }
    }
}

// ---------------- fp32 GEMM + softplus (delta projection, K=32) -----------------
template<int BM, int BN, int BK, int TM, int TN>
__global__ __launch_bounds__(256)
void gemm_softplus(const float* __restrict__ A, const float* __restrict__ Bw,
                   float* __restrict__ C, int M, int N, int K,
                   int lda, int ldb, int ldc, const float* __restrict__ bias) {
    constexpr int TX = BN / TN;
    constexpr int KV = BK / 4;
    __shared__ float As[BK][BM];
    __shared__ float Bs[BK][BN];
    int tid = threadIdx.x;
    int tx = tid % TX, ty = tid / TX;
    int bm = blockIdx.y * BM, bn = blockIdx.x * BN;
    const float* Ab = A + (size_t)bm * lda;
    const float* Bb = Bw + (size_t)bn * ldb;
    float acc[TM][TN];
    #pragma unroll
    for (int i = 0; i < TM; i++)
        #pragma unroll
        for (int j = 0; j < TN; j++) acc[i][j] = 0.f;
    for (int kt = 0; kt < K; kt += BK) {
        #pragma unroll
        for (int i = 0; i < (BM * KV) / 256; i++) {
            int idx = tid + i * 256;
            int r = idx / KV, c = idx % KV;
            float4 v = *reinterpret_cast<const float4*>(Ab + (size_t)r * lda + kt + c * 4);
            As[c*4+0][r] = v.x; As[c*4+1][r] = v.y; As[c*4+2][r] = v.z; As[c*4+3][r] = v.w;
        }
        #pragma unroll
        for (int i = 0; i < (BN * KV) / 256; i++) {
            int idx = tid + i * 256;
            int r = idx / KV, c = idx % KV;
            float4 v = *reinterpret_cast<const float4*>(Bb + (size_t)r * ldb + kt + c * 4);
            Bs[c*4+0][r] = v.x; Bs[c*4+1][r] = v.y; Bs[c*4+2][r] = v.z; Bs[c*4+3][r] = v.w;
        }
        __syncthreads();
        #pragma unroll
        for (int k = 0; k < BK; k++) {
            float ra[TM], rb[TN];
            #pragma unroll
            for (int i = 0; i < TM; i++) ra[i] = As[k][ty * TM + i];
            #pragma unroll
            for (int j = 0; j < TN; j++) rb[j] = Bs[k][tx * TN + j];
            #pragma unroll
            for (int i = 0; i < TM; i++)
                #pragma unroll
                for (int j = 0; j < TN; j++) acc[i][j] += ra[i] * rb[j];
        }
        __syncthreads();
    }
    #pragma unroll
    for (int i = 0; i < TM; i++) {
        int m = bm + ty * TM + i;
        #pragma unroll
        for (int j = 0; j < TN; j++) {
            int n = bn + tx * TN + j;
            float s = acc[i][j] + bias[n];
            float v = (s > 20.f) ? s : log1pf(__expf(s));
            C[(size_t)m * ldc + n] = v;
        }
    }
}

// ---------------- rmsnorm -> bf16 ------------------------------------------------
__global__ void rmsnorm_kernel(const float* __restrict__ x,
                               const float* __restrict__ w,
                               __nv_bfloat16* __restrict__ out) {
    int m = blockIdx.x;
    int tid = threadIdx.x;  // 128 threads, 4 floats each
    float4 v = reinterpret_cast<const float4*>(x + (size_t)m * DD)[tid];
    float ss = v.x * v.x + v.y * v.y + v.z * v.z + v.w * v.w;
    #pragma unroll
    for (int o = 16; o; o >>= 1) ss += __shfl_xor_sync(0xffffffffu, ss, o);
    __shared__ float red[4];
    if ((tid & 31) == 0) red[tid >> 5] = ss;
    __syncthreads();
    float tot = red[0] + red[1] + red[2] + red[3];
    float rs = rsqrtf(tot * (1.0f / DD) + 1e-5f);
    float4 wv = reinterpret_cast<const float4*>(w)[tid];
    __nv_bfloat162 p0 = __floats2bfloat162_rn(v.x * rs * wv.x, v.y * rs * wv.y);
    __nv_bfloat162 p1 = __floats2bfloat162_rn(v.z * rs * wv.z, v.w * rs * wv.w);
    uint2 o2 = make_uint2(*reinterpret_cast<uint32_t*>(&p0),
                          *reinterpret_cast<uint32_t*>(&p1));
    reinterpret_cast<uint2*>(out + (size_t)m * DD)[tid] = o2;
}

// ---------------- depthwise causal conv (K=4) + bias + silu (bf16 in/out) -------
__global__ void conv_silu_kernel(const __nv_bfloat16* __restrict__ xp,
                                 const float* __restrict__ w,
                                 const float* __restrict__ b,
                                 __nv_bfloat16* __restrict__ xc_bf) {
    int id = blockIdx.x * blockDim.x + threadIdx.x;
    if (id >= MM * EDIM) return;
    int e = id & (EDIM - 1);
    int mt = id >> 10;
    int t = mt & (LL - 1);
    float w0 = w[e*4+0], w1 = w[e*4+1], w2 = w[e*4+2], w3 = w[e*4+3];
    const __nv_bfloat16* base = xp + (size_t)mt * EDIM + e;
    float x0 = (t >= 3) ? __bfloat162float(base[-3 * EDIM]) : 0.f;
    float x1 = (t >= 2) ? __bfloat162float(base[-2 * EDIM]) : 0.f;
    float x2 = (t >= 1) ? __bfloat162float(base[-1 * EDIM]) : 0.f;
    float x3 = __bfloat162float(base[0]);
    float acc = b[e] + w0 * x0 + w1 * x1 + w2 * x2 + w3 * x3;
    acc = acc * (1.f / (1.f + __expf(-acc)));
    xc_bf[id] = __float2bfloat16(acc);
}

// ---------------- selective scan (smem-staged) -> bf16 y ------------------------
#define SCAN_CH 64
#define SCAN_SMEM ((3 * SCAN_CH * 128 + SCAN_CH * 32) * (int)sizeof(float))

__global__ void scan_kernel(const float* __restrict__ delta,
                            const __nv_bfloat16* __restrict__ xcb,
                            const float* __restrict__ dbc,
                            const __nv_bfloat16* __restrict__ zb,
                            const float* __restrict__ A_log,
                            const float* __restrict__ Dp,
                            __nv_bfloat16* __restrict__ y) {
    extern __shared__ float sh[];
    float* sD  = sh;                       // [CH][128]
    float* sX  = sh + SCAN_CH * 128;
    float* sZ  = sh + 2 * SCAN_CH * 128;
    float* sBC = sh + 3 * SCAN_CH * 128;   // [CH][32]

    int b = blockIdx.y;
    int tid = threadIdx.x;
    int e0 = blockIdx.x * 128;
    int e = e0 + tid;

    float a[NSTATE];
    #pragma unroll
    for (int n = 0; n < NSTATE; n++) a[n] = -__expf(A_log[(size_t)e * NSTATE + n]);
    float a0 = a[0];
    bool pw = true;
    #pragma unroll
    for (int n = 0; n < NSTATE; n++)
        pw = pw && (fabsf(a[n] - a0 * (n + 1)) <= 1e-5f * fabsf(a[n]) + 1e-12f);
    float dpar = Dp[e];

    float h[NSTATE];
    #pragma unroll
    for (int n = 0; n < NSTATE; n++) h[n] = 0.f;

    const float* dbcb = dbc + (size_t)b * LL * 64;

    for (int t0 = 0; t0 < LL; t0 += SCAN_CH) {
        __syncthreads();
        for (int i = tid; i < SCAN_CH * 32; i += 128) {
            int r = i >> 5, c = i & 31;
            sBC[i] = dbcb[(size_t)(t0 + r) * 64 + 32 + c];
        }
        for (int i = tid; i < SCAN_CH * 32; i += 128) {   // delta float4 granules
            int r = i >> 5, c4 = i & 31;
            size_t m = (size_t)(b * LL + t0 + r);
            reinterpret_cast<float4*>(sD)[i] =
                *reinterpret_cast<const float4*>(delta + m * EDIM + e0 + c4 * 4);
        }
        for (int g = tid; g < SCAN_CH * 16; g += 128) {   // bf16 x8 granules
            int r = g >> 4, c8 = g & 15;
            size_t m = (size_t)(b * LL + t0 + r);
            uint4 vx = *reinterpret_cast<const uint4*>(xcb + m * EDIM + e0 + c8 * 8);
            uint4 vz = *reinterpret_cast<const uint4*>(zb + m * EDIM + e0 + c8 * 8);
            const __nv_bfloat162* px = reinterpret_cast<const __nv_bfloat162*>(&vx);
            const __nv_bfloat162* pz = reinterpret_cast<const __nv_bfloat162*>(&vz);
            int o = r * 128 + c8 * 8;
            #pragma unroll
            for (int k = 0; k < 4; k++) {
                float2 fx = __bfloat1622float2(px[k]);
                float2 fz = __bfloat1622float2(pz[k]);
                sX[o + 2*k] = fx.x; sX[o + 2*k + 1] = fx.y;
                sZ[o + 2*k] = fz.x; sZ[o + 2*k + 1] = fz.y;
            }
        }
        __syncthreads();

        for (int i = 0; i < SCAN_CH; i++) {
            float d  = sD[i * 128 + tid];
            float xv = sX[i * 128 + tid];
            float zv = sZ[i * 128 + tid];
            float du = d * xv;
            float dA[NSTATE];
            if (pw) {
                float p = __expf(a0 * d);
                dA[0] = p;
                #pragma unroll
                for (int n = 1; n < NSTATE; n++) dA[n] = dA[n - 1] * p;
            } else {
                #pragma unroll
                for (int n = 0; n < NSTATE; n++) dA[n] = __expf(a[n] * d);
            }
            float yv = 0.f, yv2 = 0.f;
            const float* bc = sBC + i * 32;
            #pragma unroll
            for (int n = 0; n < NSTATE; n++) {
                h[n] = dA[n] * h[n] + du * bc[n];
                float c = bc[16 + n];
                if (n & 1) yv2 += h[n] * c; else yv += h[n] * c;
            }
            yv += yv2;
            float sz = zv * (1.f / (1.f + __expf(-zv)));
            size_t m = (size_t)(b * LL + t0 + i);
            y[m * EDIM + e] = __float2bfloat16((yv + dpar * xv) * sz);
        }
    }
}

// ---------------- misc -----------------------------------------------------------
__global__ void init_x(const float* __restrict__ x, const int* __restrict__ mask,
                       float* __restrict__ xb) {
    int id = blockIdx.x * blockDim.x + threadIdx.x;
    if (id < MM * DD) xb[id] = x[id] * (float)mask[id >> 9];
}

__global__ void cvt_bf16(const float* __restrict__ src, __nv_bfloat16* __restrict__ dst, int n) {
    int id = blockIdx.x * blockDim.x + threadIdx.x;
    if (id < n) dst[id] = __float2bfloat16(src[id]);
}

__global__ void tail_kernel(const float* __restrict__ xb, float* __restrict__ out) {
    int id = blockIdx.x * blockDim.x + threadIdx.x;
    if (id < BB * DD) {
        int b = id / DD, d = id % DD;
        out[id] = xb[(size_t)b * LL * DD + d];
    }
}

// ---------------- launch ---------------------------------------------------------
extern "C" void kernel_launch(void* const* d_in, const int* in_sizes, int n_in,
                              void* d_out, int out_size) {
    const float* x        = (const float*)d_in[0];
    const int*   mask     = (const int*)d_in[1];
    const float* norm_w   = (const float*)d_in[2];
    const float* in_w     = (const float*)d_in[3];
    const float* conv_w   = (const float*)d_in[4];
    const float* conv_b   = (const float*)d_in[5];
    const float* xproj_w  = (const float*)d_in[6];
    const float* dtproj_w = (const float*)d_in[7];
    const float* dtproj_b = (const float*)d_in[8];
    const float* A_log    = (const float*)d_in[9];
    const float* D_param  = (const float*)d_in[10];
    const float* out_w    = (const float*)d_in[11];

    float* xb   = (float*)d_out;
    float* tail = xb + (size_t)MM * DD;

    float *dbcp, *deltap;
    __nv_bfloat16 *ubf, *xpbf, *zbf, *xcbf, *ybf, *inwbf, *outwbf, *xprojwbf;
    cudaGetSymbolAddress((void**)&dbcp, g_dbc);
    cudaGetSymbolAddress((void**)&deltap, g_delta);
    cudaGetSymbolAddress((void**)&ubf, g_u_bf);
    cudaGetSymbolAddress((void**)&xpbf, g_xp_bf);
    cudaGetSymbolAddress((void**)&zbf, g_z_bf);
    cudaGetSymbolAddress((void**)&xcbf, g_xc_bf);
    cudaGetSymbolAddress((void**)&ybf, g_y_bf);
    cudaGetSymbolAddress((void**)&inwbf, g_inw_bf);
    cudaGetSymbolAddress((void**)&outwbf, g_outw_bf);
    cudaGetSymbolAddress((void**)&xprojwbf, g_xprojw_bf);

    cudaFuncSetAttribute(scan_kernel,
                         cudaFuncAttributeMaxDynamicSharedMemorySize, SCAN_SMEM);
    constexpr int SM128 = 4 * 128 * 128;     // 64 KB: 2 stages A + B, BN=128
    constexpr int SM64  = 2 * 128 * 128 + 2 * 64 * 128;  // 48 KB, BN=64
    cudaFuncSetAttribute(mma_gemm<128, 1>,
                         cudaFuncAttributeMaxDynamicSharedMemorySize, SM128);
    cudaFuncSetAttribute(mma_gemm<128, 2>,
                         cudaFuncAttributeMaxDynamicSharedMemorySize, SM128);
    cudaFuncSetAttribute(mma_gemm<64, 0>,
                         cudaFuncAttributeMaxDynamicSharedMemorySize, SM64);

    // weight conversions (once per call)
    {
        int n1 = NLAY * 2 * EDIM * DD;
        cvt_bf16<<<(n1 + 255) / 256, 256>>>(in_w, inwbf, n1);
        int n2 = NLAY * DD * EDIM;
        cvt_bf16<<<(n2 + 255) / 256, 256>>>(out_w, outwbf, n2);
        int n3 = NLAY * 64 * EDIM;
        cvt_bf16<<<(n3 + 255) / 256, 256>>>(xproj_w, xprojwbf, n3);
    }

    init_x<<<(MM * DD + 255) / 256, 256>>>(x, mask, xb);

    for (int l = 0; l < NLAY; l++) {
        rmsnorm_kernel<<<MM, 128>>>(xb, norm_w + l * DD, ubf);

        // xz = u @ in_w^T : M=8192, N=2048, K=512 -> split bf16 xp/z
        mma_gemm<128, 1><<<dim3(2 * EDIM / 128, MM / 128), 256, SM128>>>(
            ubf, inwbf + (size_t)l * 2 * EDIM * DD, nullptr, xpbf, zbf,
            MM, 2 * EDIM, DD, 0, nullptr);

        conv_silu_kernel<<<(MM * EDIM + 255) / 256, 256>>>(
            xpbf, conv_w + (size_t)l * EDIM * KCONV, conv_b + l * EDIM, xcbf);

        // dbc = xc @ xproj_w^T : M=8192, N=64, K=1024 (fp32 out)
        mma_gemm<64, 0><<<dim3(1, MM / 128), 256, SM64>>>(
            xcbf, xprojwbf + (size_t)l * 64 * EDIM, dbcp, nullptr, nullptr,
            MM, 64, EDIM, 64, nullptr);

        // delta = softplus(dt @ dtproj_w^T + b) : K=32, fp32 path
        gemm_softplus<128,128,16,8,8><<<dim3(EDIM / 128, MM / 128), 256>>>(
            dbcp, dtproj_w + (size_t)l * EDIM * RRANK, deltap,
            MM, EDIM, RRANK, 64, RRANK, EDIM, dtproj_b + l * EDIM);

        scan_kernel<<<dim3(EDIM / 128, BB), 128, SCAN_SMEM>>>(
            deltap, xcbf, dbcp, zbf,
            A_log + (size_t)l * EDIM * NSTATE, D_param + l * EDIM, ybf);

        // x = (x + y @ out_w^T) * mask : M=8192, N=512, K=1024
        mma_gemm<128, 2><<<dim3(DD / 128, MM / 128), 256, SM128>>>(
            ybf, outwbf + (size_t)l * DD * EDIM, xb, nullptr, nullptr,
            MM, DD, EDIM, DD, mask);
    }

    tail_kernel<<<(BB * DD + 255) / 256, 256>>>(xb, tail);
}

// round 11
// speedup vs baseline: 1.5298x; 1.5298x over previous
#include <cuda_runtime.h>
#include <cuda_bf16.h>
#include <cstdint>

#define BB 4
#define LL 2048
#define DD 512
#define NLAY 2
#define EDIM 1024
#define NSTATE 16
#define RRANK 32
#define KCONV 4
#define MM (BB*LL)   // 8192 tokens

// ---------------- scratch (static device allocations) ---------------------------
__device__ float g_dbc[(size_t)MM * 64];            // x-proj output (dt|B|C) fp32
__device__ float g_delta[(size_t)MM * EDIM];        // softplus(dt proj) fp32
__device__ __nv_bfloat16 g_u_bf[(size_t)MM * DD];       // normed input
__device__ __nv_bfloat16 g_xp_bf[(size_t)MM * EDIM];    // in-proj x half
__device__ __nv_bfloat16 g_z_bf[(size_t)MM * EDIM];     // in-proj z half
__device__ __nv_bfloat16 g_xc_bf[(size_t)MM * EDIM];    // conv+silu output
__device__ __nv_bfloat16 g_y_bf[(size_t)MM * EDIM];     // scan output
__device__ __nv_bfloat16 g_inw_bf[(size_t)NLAY * 2 * EDIM * DD];
__device__ __nv_bfloat16 g_outw_bf[(size_t)NLAY * DD * EDIM];
__device__ __nv_bfloat16 g_xprojw_bf[(size_t)NLAY * 64 * EDIM];

// ================= helpers ======================================================
__device__ __forceinline__ uint32_t smem_u32(const void* p) {
    uint32_t a;
    asm("{ .reg .u64 t; cvta.to.shared.u64 t, %1; cvt.u32.u64 %0, t; }"
        : "=r"(a) : "l"(p));
    return a;
}
#define SWZ(o) ((o) ^ (((o) >> 3) & 0x70))

__device__ __forceinline__ void cp16(uint32_t dst, const void* src) {
    asm volatile("cp.async.cg.shared.global [%0], [%1], 16;" :: "r"(dst), "l"(src));
}
__device__ __forceinline__ void cp_commit() {
    asm volatile("cp.async.commit_group;");
}
template<int N>
__device__ __forceinline__ void cp_wait() {
    asm volatile("cp.async.wait_group %0;" :: "n"(N));
}

__device__ __forceinline__ void ldsm_x4(uint32_t& r0, uint32_t& r1,
                                        uint32_t& r2, uint32_t& r3, uint32_t addr) {
    asm volatile("ldmatrix.sync.aligned.m8n8.x4.shared.b16 {%0,%1,%2,%3}, [%4];"
                 : "=r"(r0), "=r"(r1), "=r"(r2), "=r"(r3) : "r"(addr));
}
__device__ __forceinline__ void mma16816(float* d, const uint32_t* a, const uint32_t* b) {
    asm volatile("mma.sync.aligned.m16n8k16.row.col.f32.bf16.bf16.f32 "
                 "{%0,%1,%2,%3}, {%4,%5,%6,%7}, {%8,%9}, {%0,%1,%2,%3};"
                 : "+f"(d[0]), "+f"(d[1]), "+f"(d[2]), "+f"(d[3])
                 : "r"(a[0]), "r"(a[1]), "r"(a[2]), "r"(a[3]),
                   "r"(b[0]), "r"(b[1]));
}

// ================= bf16 HMMA GEMM: C[M,N] = A[M,K] @ B[N,K]^T ===================
// 3-stage cp.async pipeline; prefetch issued AFTER the barrier so the slot being
// overwritten ((kc+2)%3 == (kc-1)%3) is provably no longer being read.
// EPI 0: fp32 C store.
// EPI 1: split bf16 store: n<EDIM -> xp_bf, else -> z_bf (both [M][EDIM]).
// EPI 2: C = (C + acc) * mask[m]  (fp32 residual in-place)
template<int BN, int EPI>
__global__ __launch_bounds__(256, 2)
void mma_gemm(const __nv_bfloat16* __restrict__ A, const __nv_bfloat16* __restrict__ Bw,
              float* __restrict__ C,
              __nv_bfloat16* __restrict__ xp_bf, __nv_bfloat16* __restrict__ z_bf,
              int M, int N, int K, int ldc, const int* __restrict__ mask) {
    constexpr int BM = 128, BK = 64;
    constexpr int NW = 4, MW = 2;            // warp grid 2 (M) x 4 (N)
    constexpr int WM = BM / MW;              // 64
    constexpr int WN = BN / NW;              // 32 or 16
    constexpr int MFRAG = WM / 16;           // 4
    constexpr int NFRAG = WN / 8;            // 4 or 2
    constexpr int ASZ = BM * 128;            // bytes per A stage
    constexpr int BSZ = BN * 128;
    constexpr int STG = 3;

    extern __shared__ __align__(1024) char dynsmem[];
    char* sA = dynsmem;                      // STG stages of A then B
    char* sB = dynsmem + STG * ASZ;

    int tid = threadIdx.x;
    int wid = tid >> 5, lane = tid & 31;
    int bm = blockIdx.y * BM, bn = blockIdx.x * BN;
    int wm = (wid / NW) * WM;
    int wn = (wid % NW) * WN;
    uint32_t sAb = smem_u32(sA), sBb = smem_u32(sB);

    // per-lane ldmatrix base offsets (within a stage, without k-step term)
    uint32_t aBase[MFRAG];
    #pragma unroll
    for (int i = 0; i < MFRAG; i++)
        aBase[i] = (uint32_t)((wm + i * 16 + (lane & 15)) * 128 + (lane >> 4) * 16);
    uint32_t bBase[NFRAG / 2];
    #pragma unroll
    for (int j = 0; j < NFRAG / 2; j++)
        bBase[j] = (uint32_t)((wn + j * 16 + (lane & 7) + ((lane >> 4) & 1) * 8) * 128
                              + ((lane >> 3) & 1) * 16);

    float acc[MFRAG][NFRAG][4];
    #pragma unroll
    for (int i = 0; i < MFRAG; i++)
        #pragma unroll
        for (int j = 0; j < NFRAG; j++)
            #pragma unroll
            for (int q = 0; q < 4; q++) acc[i][j][q] = 0.f;

    const int nk = K / BK;

#define LOAD_STAGE(kc, st) do {                                                 \
        _Pragma("unroll")                                                       \
        for (int i = 0; i < (BM * 8) / 256; i++) {                              \
            int idx = tid + i * 256;                                            \
            int r = idx >> 3, c8 = idx & 7;                                     \
            cp16(sAb + (st) * ASZ + SWZ((uint32_t)(r * 128 + c8 * 16)),         \
                 A + (size_t)(bm + r) * K + (kc) * 64 + c8 * 8);                \
        }                                                                       \
        _Pragma("unroll")                                                       \
        for (int i = 0; i < (BN * 8) / 256; i++) {                              \
            int idx = tid + i * 256;                                            \
            int r = idx >> 3, c8 = idx & 7;                                     \
            cp16(sBb + (st) * BSZ + SWZ((uint32_t)(r * 128 + c8 * 16)),         \
                 Bw + (size_t)(bn + r) * K + (kc) * 64 + c8 * 8);               \
        }                                                                       \
    } while (0)

    // prologue: stages 0 and 1 in flight, one commit group each
    LOAD_STAGE(0, 0); cp_commit();
    LOAD_STAGE(1, 1); cp_commit();

    int st = 0;
    for (int kc = 0; kc < nk; kc++) {
        // groups committed so far: 2 + kc. Stage kc is group #kc; the only
        // group allowed outstanding is stage kc+1 -> wait_group<1>.
        cp_wait<1>();
        __syncthreads();
        // prefetch stage kc+2 into slot (kc+2)%3 == (kc-1)%3 — safe NOW:
        // every warp passed the barrier, so iteration kc-1's reads are done.
        if (kc + 2 < nk) {
            int st2 = st + 2 >= STG ? st + 2 - STG : st + 2;
            LOAD_STAGE(kc + 2, st2);
        }
        cp_commit();            // uniform one-group-per-iteration

        uint32_t aS = sAb + st * ASZ, bS = sBb + st * BSZ;
        #pragma unroll
        for (int ks = 0; ks < 4; ks++) {
            uint32_t af[MFRAG][4];
            #pragma unroll
            for (int i = 0; i < MFRAG; i++)
                ldsm_x4(af[i][0], af[i][1], af[i][2], af[i][3],
                        aS + SWZ(aBase[i] + ks * 32));
            uint32_t bf[NFRAG][2];
            #pragma unroll
            for (int j = 0; j < NFRAG / 2; j++) {
                uint32_t r0, r1, r2, r3;
                ldsm_x4(r0, r1, r2, r3, bS + SWZ(bBase[j] + ks * 32));
                bf[j * 2][0] = r0; bf[j * 2][1] = r1;
                bf[j * 2 + 1][0] = r2; bf[j * 2 + 1][1] = r3;
            }
            #pragma unroll
            for (int i = 0; i < MFRAG; i++)
                #pragma unroll
                for (int j = 0; j < NFRAG; j++)
                    mma16816(acc[i][j], af[i], bf[j]);
        }
        st = (st + 1 == STG) ? 0 : st + 1;
    }
#undef LOAD_STAGE

    // ---- epilogue (register-only sources; no smem reuse) ----
    bool isz = false;
    __nv_bfloat16* OB = nullptr;
    if (EPI == 1) { isz = (bn >= EDIM); OB = isz ? z_bf : xp_bf; }
    #pragma unroll
    for (int i = 0; i < MFRAG; i++) {
        int r0 = bm + wm + i * 16 + (lane >> 2);
        int r1 = r0 + 8;
        float mk0 = 1.f, mk1 = 1.f;
        if (EPI == 2) { mk0 = (float)mask[r0]; mk1 = (float)mask[r1]; }
        #pragma unroll
        for (int j = 0; j < NFRAG; j++) {
            int c = bn + wn + j * 8 + (lane & 3) * 2;
            if (EPI == 1) {
                int cb = c - (isz ? EDIM : 0);
                __nv_bfloat162 b0 = __floats2bfloat162_rn(acc[i][j][0], acc[i][j][1]);
                __nv_bfloat162 b1 = __floats2bfloat162_rn(acc[i][j][2], acc[i][j][3]);
                *reinterpret_cast<__nv_bfloat162*>(OB + (size_t)r0 * EDIM + cb) = b0;
                *reinterpret_cast<__nv_bfloat162*>(OB + (size_t)r1 * EDIM + cb) = b1;
            } else {
                size_t i0 = (size_t)r0 * ldc + c;
                size_t i1 = (size_t)r1 * ldc + c;
                float2 v0 = make_float2(acc[i][j][0], acc[i][j][1]);
                float2 v1 = make_float2(acc[i][j][2], acc[i][j][3]);
                if (EPI == 2) {
                    float2 o0 = *reinterpret_cast<float2*>(C + i0);
                    float2 o1 = *reinterpret_cast<float2*>(C + i1);
                    v0 = make_float2((o0.x + v0.x) * mk0, (o0.y + v0.y) * mk0);
                    v1 = make_float2((o1.x + v1.x) * mk1, (o1.y + v1.y) * mk1);
                }
                *reinterpret_cast<float2*>(C + i0) = v0;
                *reinterpret_cast<float2*>(C + i1) = v1;
            }
        }
    }
}

// ---------------- fp32 GEMM + softplus (delta projection, K=32) -----------------
template<int BM, int BN, int BK, int TM, int TN>
__global__ __launch_bounds__(256)
void gemm_softplus(const float* __restrict__ A, const float* __restrict__ Bw,
                   float* __restrict__ C, int M, int N, int K,
                   int lda, int ldb, int ldc, const float* __restrict__ bias) {
    constexpr int TX = BN / TN;
    constexpr int KV = BK / 4;
    __shared__ float As[BK][BM];
    __shared__ float Bs[BK][BN];
    int tid = threadIdx.x;
    int tx = tid % TX, ty = tid / TX;
    int bm = blockIdx.y * BM, bn = blockIdx.x * BN;
    const float* Ab = A + (size_t)bm * lda;
    const float* Bb = Bw + (size_t)bn * ldb;
    float acc[TM][TN];
    #pragma unroll
    for (int i = 0; i < TM; i++)
        #pragma unroll
        for (int j = 0; j < TN; j++) acc[i][j] = 0.f;
    for (int kt = 0; kt < K; kt += BK) {
        #pragma unroll
        for (int i = 0; i < (BM * KV) / 256; i++) {
            int idx = tid + i * 256;
            int r = idx / KV, c = idx % KV;
            float4 v = *reinterpret_cast<const float4*>(Ab + (size_t)r * lda + kt + c * 4);
            As[c*4+0][r] = v.x; As[c*4+1][r] = v.y; As[c*4+2][r] = v.z; As[c*4+3][r] = v.w;
        }
        #pragma unroll
        for (int i = 0; i < (BN * KV) / 256; i++) {
            int idx = tid + i * 256;
            int r = idx / KV, c = idx % KV;
            float4 v = *reinterpret_cast<const float4*>(Bb + (size_t)r * ldb + kt + c * 4);
            Bs[c*4+0][r] = v.x; Bs[c*4+1][r] = v.y; Bs[c*4+2][r] = v.z; Bs[c*4+3][r] = v.w;
        }
        __syncthreads();
        #pragma unroll
        for (int k = 0; k < BK; k++) {
            float ra[TM], rb[TN];
            #pragma unroll
            for (int i = 0; i < TM; i++) ra[i] = As[k][ty * TM + i];
            #pragma unroll
            for (int j = 0; j < TN; j++) rb[j] = Bs[k][tx * TN + j];
            #pragma unroll
            for (int i = 0; i < TM; i++)
                #pragma unroll
                for (int j = 0; j < TN; j++) acc[i][j] += ra[i] * rb[j];
        }
        __syncthreads();
    }
    #pragma unroll
    for (int i = 0; i < TM; i++) {
        int m = bm + ty * TM + i;
        #pragma unroll
        for (int j = 0; j < TN; j++) {
            int n = bn + tx * TN + j;
            float s = acc[i][j] + bias[n];
            float v = (s > 20.f) ? s : log1pf(__expf(s));
            C[(size_t)m * ldc + n] = v;
        }
    }
}

// ---------------- rmsnorm -> bf16 ------------------------------------------------
__global__ void rmsnorm_kernel(const float* __restrict__ x,
                               const float* __restrict__ w,
                               __nv_bfloat16* __restrict__ out) {
    int m = blockIdx.x;
    int tid = threadIdx.x;  // 128 threads, 4 floats each
    float4 v = reinterpret_cast<const float4*>(x + (size_t)m * DD)[tid];
    float ss = v.x * v.x + v.y * v.y + v.z * v.z + v.w * v.w;
    #pragma unroll
    for (int o = 16; o; o >>= 1) ss += __shfl_xor_sync(0xffffffffu, ss, o);
    __shared__ float red[4];
    if ((tid & 31) == 0) red[tid >> 5] = ss;
    __syncthreads();
    float tot = red[0] + red[1] + red[2] + red[3];
    float rs = rsqrtf(tot * (1.0f / DD) + 1e-5f);
    float4 wv = reinterpret_cast<const float4*>(w)[tid];
    __nv_bfloat162 p0 = __floats2bfloat162_rn(v.x * rs * wv.x, v.y * rs * wv.y);
    __nv_bfloat162 p1 = __floats2bfloat162_rn(v.z * rs * wv.z, v.w * rs * wv.w);
    uint2 o2 = make_uint2(*reinterpret_cast<uint32_t*>(&p0),
                          *reinterpret_cast<uint32_t*>(&p1));
    reinterpret_cast<uint2*>(out + (size_t)m * DD)[tid] = o2;
}

// ---------------- depthwise causal conv (K=4) + bias + silu (bf16 in/out) -------
__global__ void conv_silu_kernel(const __nv_bfloat16* __restrict__ xp,
                                 const float* __restrict__ w,
                                 const float* __restrict__ b,
                                 __nv_bfloat16* __restrict__ xc_bf) {
    int id = blockIdx.x * blockDim.x + threadIdx.x;
    if (id >= MM * EDIM) return;
    int e = id & (EDIM - 1);
    int mt = id >> 10;
    int t = mt & (LL - 1);
    float w0 = w[e*4+0], w1 = w[e*4+1], w2 = w[e*4+2], w3 = w[e*4+3];
    const __nv_bfloat16* base = xp + (size_t)mt * EDIM + e;
    float x0 = (t >= 3) ? __bfloat162float(base[-3 * EDIM]) : 0.f;
    float x1 = (t >= 2) ? __bfloat162float(base[-2 * EDIM]) : 0.f;
    float x2 = (t >= 1) ? __bfloat162float(base[-1 * EDIM]) : 0.f;
    float x3 = __bfloat162float(base[0]);
    float acc = b[e] + w0 * x0 + w1 * x1 + w2 * x2 + w3 * x3;
    acc = acc * (1.f / (1.f + __expf(-acc)));
    xc_bf[id] = __float2bfloat16(acc);
}

// ---------------- selective scan (smem-staged) -> bf16 y ------------------------
#define SCAN_CH 64
#define SCAN_SMEM ((3 * SCAN_CH * 128 + SCAN_CH * 32) * (int)sizeof(float))

__global__ void scan_kernel(const float* __restrict__ delta,
                            const __nv_bfloat16* __restrict__ xcb,
                            const float* __restrict__ dbc,
                            const __nv_bfloat16* __restrict__ zb,
                            const float* __restrict__ A_log,
                            const float* __restrict__ Dp,
                            __nv_bfloat16* __restrict__ y) {
    extern __shared__ float sh[];
    float* sD  = sh;                       // [CH][128]
    float* sX  = sh + SCAN_CH * 128;
    float* sZ  = sh + 2 * SCAN_CH * 128;
    float* sBC = sh + 3 * SCAN_CH * 128;   // [CH][32]

    int b = blockIdx.y;
    int tid = threadIdx.x;
    int e0 = blockIdx.x * 128;
    int e = e0 + tid;

    float a[NSTATE];
    #pragma unroll
    for (int n = 0; n < NSTATE; n++) a[n] = -__expf(A_log[(size_t)e * NSTATE + n]);
    float a0 = a[0];
    bool pw = true;
    #pragma unroll
    for (int n = 0; n < NSTATE; n++)
        pw = pw && (fabsf(a[n] - a0 * (n + 1)) <= 1e-5f * fabsf(a[n]) + 1e-12f);
    float dpar = Dp[e];

    float h[NSTATE];
    #pragma unroll
    for (int n = 0; n < NSTATE; n++) h[n] = 0.f;

    const float* dbcb = dbc + (size_t)b * LL * 64;

    for (int t0 = 0; t0 < LL; t0 += SCAN_CH) {
        __syncthreads();
        for (int i = tid; i < SCAN_CH * 32; i += 128) {
            int r = i >> 5, c = i & 31;
            sBC[i] = dbcb[(size_t)(t0 + r) * 64 + 32 + c];
        }
        for (int i = tid; i < SCAN_CH * 32; i += 128) {   // delta float4 granules
            int r = i >> 5, c4 = i & 31;
            size_t m = (size_t)(b * LL + t0 + r);
            reinterpret_cast<float4*>(sD)[i] =
                *reinterpret_cast<const float4*>(delta + m * EDIM + e0 + c4 * 4);
        }
        for (int g = tid; g < SCAN_CH * 16; g += 128) {   // bf16 x8 granules
            int r = g >> 4, c8 = g & 15;
            size_t m = (size_t)(b * LL + t0 + r);
            uint4 vx = *reinterpret_cast<const uint4*>(xcb + m * EDIM + e0 + c8 * 8);
            uint4 vz = *reinterpret_cast<const uint4*>(zb + m * EDIM + e0 + c8 * 8);
            const __nv_bfloat162* px = reinterpret_cast<const __nv_bfloat162*>(&vx);
            const __nv_bfloat162* pz = reinterpret_cast<const __nv_bfloat162*>(&vz);
            int o = r * 128 + c8 * 8;
            #pragma unroll
            for (int k = 0; k < 4; k++) {
                float2 fx = __bfloat1622float2(px[k]);
                float2 fz = __bfloat1622float2(pz[k]);
                sX[o + 2*k] = fx.x; sX[o + 2*k + 1] = fx.y;
                sZ[o + 2*k] = fz.x; sZ[o + 2*k + 1] = fz.y;
            }
        }
        __syncthreads();

        for (int i = 0; i < SCAN_CH; i++) {
            float d  = sD[i * 128 + tid];
            float xv = sX[i * 128 + tid];
            float zv = sZ[i * 128 + tid];
            float du = d * xv;
            float dA[NSTATE];
            if (pw) {
                float p = __expf(a0 * d);
                dA[0] = p;
                #pragma unroll
                for (int n = 1; n < NSTATE; n++) dA[n] = dA[n - 1] * p;
            } else {
                #pragma unroll
                for (int n = 0; n < NSTATE; n++) dA[n] = __expf(a[n] * d);
            }
            float yv = 0.f, yv2 = 0.f;
            const float* bc = sBC + i * 32;
            #pragma unroll
            for (int n = 0; n < NSTATE; n++) {
                h[n] = dA[n] * h[n] + du * bc[n];
                float c = bc[16 + n];
                if (n & 1) yv2 += h[n] * c; else yv += h[n] * c;
            }
            yv += yv2;
            float sz = zv * (1.f / (1.f + __expf(-zv)));
            size_t m = (size_t)(b * LL + t0 + i);
            y[m * EDIM + e] = __float2bfloat16((yv + dpar * xv) * sz);
        }
    }
}

// ---------------- misc -----------------------------------------------------------
__global__ void init_x(const float* __restrict__ x, const int* __restrict__ mask,
                       float* __restrict__ xb) {
    int id = blockIdx.x * blockDim.x + threadIdx.x;
    if (id < MM * DD) xb[id] = x[id] * (float)mask[id >> 9];
}

__global__ void cvt_bf16(const float* __restrict__ src, __nv_bfloat16* __restrict__ dst, int n) {
    int id = blockIdx.x * blockDim.x + threadIdx.x;
    if (id < n) dst[id] = __float2bfloat16(src[id]);
}

__global__ void tail_kernel(const float* __restrict__ xb, float* __restrict__ out) {
    int id = blockIdx.x * blockDim.x + threadIdx.x;
    if (id < BB * DD) {
        int b = id / DD, d = id % DD;
        out[id] = xb[(size_t)b * LL * DD + d];
    }
}

// ---------------- launch ---------------------------------------------------------
extern "C" void kernel_launch(void* const* d_in, const int* in_sizes, int n_in,
                              void* d_out, int out_size) {
    const float* x        = (const float*)d_in[0];
    const int*   mask     = (const int*)d_in[1];
    const float* norm_w   = (const float*)d_in[2];
    const float* in_w     = (const float*)d_in[3];
    const float* conv_w   = (const float*)d_in[4];
    const float* conv_b   = (const float*)d_in[5];
    const float* xproj_w  = (const float*)d_in[6];
    const float* dtproj_w = (const float*)d_in[7];
    const float* dtproj_b = (const float*)d_in[8];
    const float* A_log    = (const float*)d_in[9];
    const float* D_param  = (const float*)d_in[10];
    const float* out_w    = (const float*)d_in[11];

    float* xb   = (float*)d_out;
    float* tail = xb + (size_t)MM * DD;

    float *dbcp, *deltap;
    __nv_bfloat16 *ubf, *xpbf, *zbf, *xcbf, *ybf, *inwbf, *outwbf, *xprojwbf;
    cudaGetSymbolAddress((void**)&dbcp, g_dbc);
    cudaGetSymbolAddress((void**)&deltap, g_delta);
    cudaGetSymbolAddress((void**)&ubf, g_u_bf);
    cudaGetSymbolAddress((void**)&xpbf, g_xp_bf);
    cudaGetSymbolAddress((void**)&zbf, g_z_bf);
    cudaGetSymbolAddress((void**)&xcbf, g_xc_bf);
    cudaGetSymbolAddress((void**)&ybf, g_y_bf);
    cudaGetSymbolAddress((void**)&inwbf, g_inw_bf);
    cudaGetSymbolAddress((void**)&outwbf, g_outw_bf);
    cudaGetSymbolAddress((void**)&xprojwbf, g_xprojw_bf);

    cudaFuncSetAttribute(scan_kernel,
                         cudaFuncAttributeMaxDynamicSharedMemorySize, SCAN_SMEM);
    constexpr int SM128 = 3 * (128 * 128 + 128 * 128);   // 96 KB: 3 stages, BN=128
    constexpr int SM64  = 3 * (128 * 128 + 64 * 128);    // 72 KB, BN=64
    cudaFuncSetAttribute(mma_gemm<128, 1>,
                         cudaFuncAttributeMaxDynamicSharedMemorySize, SM128);
    cudaFuncSetAttribute(mma_gemm<128, 2>,
                         cudaFuncAttributeMaxDynamicSharedMemorySize, SM128);
    cudaFuncSetAttribute(mma_gemm<64, 0>,
                         cudaFuncAttributeMaxDynamicSharedMemorySize, SM64);

    // weight conversions (once per call)
    {
        int n1 = NLAY * 2 * EDIM * DD;
        cvt_bf16<<<(n1 + 255) / 256, 256>>>(in_w, inwbf, n1);
        int n2 = NLAY * DD * EDIM;
        cvt_bf16<<<(n2 + 255) / 256, 256>>>(out_w, outwbf, n2);
        int n3 = NLAY * 64 * EDIM;
        cvt_bf16<<<(n3 + 255) / 256, 256>>>(xproj_w, xprojwbf, n3);
    }

    init_x<<<(MM * DD + 255) / 256, 256>>>(x, mask, xb);

    for (int l = 0; l < NLAY; l++) {
        rmsnorm_kernel<<<MM, 128>>>(xb, norm_w + l * DD, ubf);

        // xz = u @ in_w^T : M=8192, N=2048, K=512 -> split bf16 xp/z
        mma_gemm<128, 1><<<dim3(2 * EDIM / 128, MM / 128), 256, SM128>>>(
            ubf, inwbf + (size_t)l * 2 * EDIM * DD, nullptr, xpbf, zbf,
            MM, 2 * EDIM, DD, 0, nullptr);

        conv_silu_kernel<<<(MM * EDIM + 255) / 256, 256>>>(
            xpbf, conv_w + (size_t)l * EDIM * KCONV, conv_b + l * EDIM, xcbf);

        // dbc = xc @ xproj_w^T : M=8192, N=64, K=1024 (fp32 out)
        mma_gemm<64, 0><<<dim3(1, MM / 128), 256, SM64>>>(
            xcbf, xprojwbf + (size_t)l * 64 * EDIM, dbcp, nullptr, nullptr,
            MM, 64, EDIM, 64, nullptr);

        // delta = softplus(dt @ dtproj_w^T + b) : K=32, fp32 path
        gemm_softplus<128,128,16,8,8><<<dim3(EDIM / 128, MM / 128), 256>>>(
            dbcp, dtproj_w + (size_t)l * EDIM * RRANK, deltap,
            MM, EDIM, RRANK, 64, RRANK, EDIM, dtproj_b + l * EDIM);

        scan_kernel<<<dim3(EDIM / 128, BB), 128, SCAN_SMEM>>>(
            deltap, xcbf, dbcp, zbf,
            A_log + (size_t)l * EDIM * NSTATE, D_param + l * EDIM, ybf);

        // x = (x + y @ out_w^T) * mask : M=8192, N=512, K=1024
        mma_gemm<128, 2><<<dim3(DD / 128, MM / 128), 256, SM128>>>(
            ybf, outwbf + (size_t)l * DD * EDIM, xb, nullptr, nullptr,
            MM, DD, EDIM, DD, mask);
    }

    tail_kernel<<<(BB * DD + 255) / 256, 256>>>(xb, tail);
}

// round 15
// speedup vs baseline: 3.3374x; 2.1816x over previous
#include <cuda_runtime.h>
#include <cuda_bf16.h>
#include <cstdint>

#define BB 4
#define LL 2048
#define DD 512
#define NLAY 2
#define EDIM 1024
#define NSTATE 16
#define RRANK 32
#define KCONV 4
#define MM (BB*LL)   // 8192 tokens
#define NCHUNK 16
#define CHLEN 128    // LL / NCHUNK

// ---------------- scratch (static device allocations) ---------------------------
__device__ float g_dbc[(size_t)MM * 64];            // x-proj output (dt|B|C) fp32
__device__ float g_delta[(size_t)MM * EDIM];        // softplus(dt proj) fp32
__device__ float g_ypart[(size_t)MM * EDIM];        // local scan output fp32
__device__ float g_csum[(size_t)MM * EDIM];         // within-chunk cumsum(delta)
__device__ float g_hstate[(size_t)BB * NCHUNK * EDIM * NSTATE]; // h_end -> h_in
__device__ float g_meta[EDIM * 2];                  // {a0, pw} per channel
__device__ __nv_bfloat16 g_u_bf[(size_t)MM * DD];       // normed input
__device__ __nv_bfloat16 g_xp_bf[(size_t)MM * EDIM];    // in-proj x half
__device__ __nv_bfloat16 g_z_bf[(size_t)MM * EDIM];     // in-proj z half
__device__ __nv_bfloat16 g_xc_bf[(size_t)MM * EDIM];    // conv+silu output
__device__ __nv_bfloat16 g_y_bf[(size_t)MM * EDIM];     // scan output
__device__ __nv_bfloat16 g_inw_bf[(size_t)NLAY * 2 * EDIM * DD];
__device__ __nv_bfloat16 g_outw_bf[(size_t)NLAY * DD * EDIM];
__device__ __nv_bfloat16 g_xprojw_bf[(size_t)NLAY * 64 * EDIM];

// ================= helpers ======================================================
__device__ __forceinline__ uint32_t smem_u32(const void* p) {
    uint32_t a;
    asm("{ .reg .u64 t; cvta.to.shared.u64 t, %1; cvt.u32.u64 %0, t; }"
        : "=r"(a) : "l"(p));
    return a;
}
#define SWZ(o) ((o) ^ (((o) >> 3) & 0x70))

__device__ __forceinline__ void cp16(uint32_t dst, const void* src) {
    asm volatile("cp.async.cg.shared.global [%0], [%1], 16;" :: "r"(dst), "l"(src));
}
__device__ __forceinline__ void cp_commit() {
    asm volatile("cp.async.commit_group;");
}
template<int N>
__device__ __forceinline__ void cp_wait() {
    asm volatile("cp.async.wait_group %0;" :: "n"(N));
}

__device__ __forceinline__ void ldsm_x4(uint32_t& r0, uint32_t& r1,
                                        uint32_t& r2, uint32_t& r3, uint32_t addr) {
    asm volatile("ldmatrix.sync.aligned.m8n8.x4.shared.b16 {%0,%1,%2,%3}, [%4];"
                 : "=r"(r0), "=r"(r1), "=r"(r2), "=r"(r3) : "r"(addr));
}
__device__ __forceinline__ void mma16816(float* d, const uint32_t* a, const uint32_t* b) {
    asm volatile("mma.sync.aligned.m16n8k16.row.col.f32.bf16.bf16.f32 "
                 "{%0,%1,%2,%3}, {%4,%5,%6,%7}, {%8,%9}, {%0,%1,%2,%3};"
                 : "+f"(d[0]), "+f"(d[1]), "+f"(d[2]), "+f"(d[3])
                 : "r"(a[0]), "r"(a[1]), "r"(a[2]), "r"(a[3]),
                   "r"(b[0]), "r"(b[1]));
}

// ================= bf16 HMMA GEMM: C[M,N] = A[M,K] @ B[N,K]^T ===================
// 3-stage cp.async pipeline; prefetch after the barrier (slot provably free).
// EPI 0: fp32 C store.
// EPI 1: split bf16 store: n<EDIM -> xp_bf, else -> z_bf (both [M][EDIM]).
// EPI 2: C = (C + acc) * mask[m]  (fp32 residual in-place)
template<int BN, int EPI>
__global__ __launch_bounds__(256, 2)
void mma_gemm(const __nv_bfloat16* __restrict__ A, const __nv_bfloat16* __restrict__ Bw,
              float* __restrict__ C,
              __nv_bfloat16* __restrict__ xp_bf, __nv_bfloat16* __restrict__ z_bf,
              int M, int N, int K, int ldc, const int* __restrict__ mask) {
    constexpr int BM = 128, BK = 64;
    constexpr int NW = 4, MW = 2;
    constexpr int WM = BM / MW;              // 64
    constexpr int WN = BN / NW;              // 32 or 16
    constexpr int MFRAG = WM / 16;           // 4
    constexpr int NFRAG = WN / 8;            // 4 or 2
    constexpr int ASZ = BM * 128;
    constexpr int BSZ = BN * 128;
    constexpr int STG = 3;

    extern __shared__ __align__(1024) char dynsmem[];
    char* sA = dynsmem;
    char* sB = dynsmem + STG * ASZ;

    int tid = threadIdx.x;
    int wid = tid >> 5, lane = tid & 31;
    int bm = blockIdx.y * BM, bn = blockIdx.x * BN;
    int wm = (wid / NW) * WM;
    int wn = (wid % NW) * WN;
    uint32_t sAb = smem_u32(sA), sBb = smem_u32(sB);

    uint32_t aBase[MFRAG];
    #pragma unroll
    for (int i = 0; i < MFRAG; i++)
        aBase[i] = (uint32_t)((wm + i * 16 + (lane & 15)) * 128 + (lane >> 4) * 16);
    uint32_t bBase[NFRAG / 2];
    #pragma unroll
    for (int j = 0; j < NFRAG / 2; j++)
        bBase[j] = (uint32_t)((wn + j * 16 + (lane & 7) + ((lane >> 4) & 1) * 8) * 128
                              + ((lane >> 3) & 1) * 16);

    float acc[MFRAG][NFRAG][4];
    #pragma unroll
    for (int i = 0; i < MFRAG; i++)
        #pragma unroll
        for (int j = 0; j < NFRAG; j++)
            #pragma unroll
            for (int q = 0; q < 4; q++) acc[i][j][q] = 0.f;

    const int nk = K / BK;

#define LOAD_STAGE(kc, st) do {                                                 \
        _Pragma("unroll")                                                       \
        for (int i = 0; i < (BM * 8) / 256; i++) {                              \
            int idx = tid + i * 256;                                            \
            int r = idx >> 3, c8 = idx & 7;                                     \
            cp16(sAb + (st) * ASZ + SWZ((uint32_t)(r * 128 + c8 * 16)),         \
                 A + (size_t)(bm + r) * K + (kc) * 64 + c8 * 8);                \
        }                                                                       \
        _Pragma("unroll")                                                       \
        for (int i = 0; i < (BN * 8) / 256; i++) {                              \
            int idx = tid + i * 256;                                            \
            int r = idx >> 3, c8 = idx & 7;                                     \
            cp16(sBb + (st) * BSZ + SWZ((uint32_t)(r * 128 + c8 * 16)),         \
                 Bw + (size_t)(bn + r) * K + (kc) * 64 + c8 * 8);               \
        }                                                                       \
    } while (0)

    LOAD_STAGE(0, 0); cp_commit();
    LOAD_STAGE(1, 1); cp_commit();

    int st = 0;
    for (int kc = 0; kc < nk; kc++) {
        cp_wait<1>();
        __syncthreads();
        if (kc + 2 < nk) {
            int st2 = st + 2 >= STG ? st + 2 - STG : st + 2;
            LOAD_STAGE(kc + 2, st2);
        }
        cp_commit();

        uint32_t aS = sAb + st * ASZ, bS = sBb + st * BSZ;
        #pragma unroll
        for (int ks = 0; ks < 4; ks++) {
            uint32_t af[MFRAG][4];
            #pragma unroll
            for (int i = 0; i < MFRAG; i++)
                ldsm_x4(af[i][0], af[i][1], af[i][2], af[i][3],
                        aS + SWZ(aBase[i] + ks * 32));
            uint32_t bf[NFRAG][2];
            #pragma unroll
            for (int j = 0; j < NFRAG / 2; j++) {
                uint32_t r0, r1, r2, r3;
                ldsm_x4(r0, r1, r2, r3, bS + SWZ(bBase[j] + ks * 32));
                bf[j * 2][0] = r0; bf[j * 2][1] = r1;
                bf[j * 2 + 1][0] = r2; bf[j * 2 + 1][1] = r3;
            }
            #pragma unroll
            for (int i = 0; i < MFRAG; i++)
                #pragma unroll
                for (int j = 0; j < NFRAG; j++)
                    mma16816(acc[i][j], af[i], bf[j]);
        }
        st = (st + 1 == STG) ? 0 : st + 1;
    }
#undef LOAD_STAGE

    // ---- epilogue ----
    bool isz = false;
    __nv_bfloat16* OB = nullptr;
    if (EPI == 1) { isz = (bn >= EDIM); OB = isz ? z_bf : xp_bf; }
    #pragma unroll
    for (int i = 0; i < MFRAG; i++) {
        int r0 = bm + wm + i * 16 + (lane >> 2);
        int r1 = r0 + 8;
        float mk0 = 1.f, mk1 = 1.f;
        if (EPI == 2) { mk0 = (float)mask[r0]; mk1 = (float)mask[r1]; }
        #pragma unroll
        for (int j = 0; j < NFRAG; j++) {
            int c = bn + wn + j * 8 + (lane & 3) * 2;
            if (EPI == 1) {
                int cb = c - (isz ? EDIM : 0);
                __nv_bfloat162 b0 = __floats2bfloat162_rn(acc[i][j][0], acc[i][j][1]);
                __nv_bfloat162 b1 = __floats2bfloat162_rn(acc[i][j][2], acc[i][j][3]);
                *reinterpret_cast<__nv_bfloat162*>(OB + (size_t)r0 * EDIM + cb) = b0;
                *reinterpret_cast<__nv_bfloat162*>(OB + (size_t)r1 * EDIM + cb) = b1;
            } else {
                size_t i0 = (size_t)r0 * ldc + c;
                size_t i1 = (size_t)r1 * ldc + c;
                float2 v0 = make_float2(acc[i][j][0], acc[i][j][1]);
                float2 v1 = make_float2(acc[i][j][2], acc[i][j][3]);
                if (EPI == 2) {
                    float2 o0 = *reinterpret_cast<float2*>(C + i0);
                    float2 o1 = *reinterpret_cast<float2*>(C + i1);
                    v0 = make_float2((o0.x + v0.x) * mk0, (o0.y + v0.y) * mk0);
                    v1 = make_float2((o1.x + v1.x) * mk1, (o1.y + v1.y) * mk1);
                }
                *reinterpret_cast<float2*>(C + i0) = v0;
                *reinterpret_cast<float2*>(C + i1) = v1;
            }
        }
    }
}

// ---------------- fp32 GEMM + softplus (delta projection, K=32) -----------------
template<int BM, int BN, int BK, int TM, int TN>
__global__ __launch_bounds__(256)
void gemm_softplus(const float* __restrict__ A, const float* __restrict__ Bw,
                   float* __restrict__ C, int M, int N, int K,
                   int lda, int ldb, int ldc, const float* __restrict__ bias) {
    constexpr int TX = BN / TN;
    constexpr int KV = BK / 4;
    __shared__ float As[BK][BM];
    __shared__ float Bs[BK][BN];
    int tid = threadIdx.x;
    int tx = tid % TX, ty = tid / TX;
    int bm = blockIdx.y * BM, bn = blockIdx.x * BN;
    const float* Ab = A + (size_t)bm * lda;
    const float* Bb = Bw + (size_t)bn * ldb;
    float acc[TM][TN];
    #pragma unroll
    for (int i = 0; i < TM; i++)
        #pragma unroll
        for (int j = 0; j < TN; j++) acc[i][j] = 0.f;
    for (int kt = 0; kt < K; kt += BK) {
        #pragma unroll
        for (int i = 0; i < (BM * KV) / 256; i++) {
            int idx = tid + i * 256;
            int r = idx / KV, c = idx % KV;
            float4 v = *reinterpret_cast<const float4*>(Ab + (size_t)r * lda + kt + c * 4);
            As[c*4+0][r] = v.x; As[c*4+1][r] = v.y; As[c*4+2][r] = v.z; As[c*4+3][r] = v.w;
        }
        #pragma unroll
        for (int i = 0; i < (BN * KV) / 256; i++) {
            int idx = tid + i * 256;
            int r = idx / KV, c = idx % KV;
            float4 v = *reinterpret_cast<const float4*>(Bb + (size_t)r * ldb + kt + c * 4);
            Bs[c*4+0][r] = v.x; Bs[c*4+1][r] = v.y; Bs[c*4+2][r] = v.z; Bs[c*4+3][r] = v.w;
        }
        __syncthreads();
        #pragma unroll
        for (int k = 0; k < BK; k++) {
            float ra[TM], rb[TN];
            #pragma unroll
            for (int i = 0; i < TM; i++) ra[i] = As[k][ty * TM + i];
            #pragma unroll
            for (int j = 0; j < TN; j++) rb[j] = Bs[k][tx * TN + j];
            #pragma unroll
            for (int i = 0; i < TM; i++)
                #pragma unroll
                for (int j = 0; j < TN; j++) acc[i][j] += ra[i] * rb[j];
        }
        __syncthreads();
    }
    #pragma unroll
    for (int i = 0; i < TM; i++) {
        int m = bm + ty * TM + i;
        #pragma unroll
        for (int j = 0; j < TN; j++) {
            int n = bn + tx * TN + j;
            float s = acc[i][j] + bias[n];
            float v = (s > 20.f) ? s : log1pf(__expf(s));
            C[(size_t)m * ldc + n] = v;
        }
    }
}

// ---------------- rmsnorm -> bf16 ------------------------------------------------
__global__ void rmsnorm_kernel(const float* __restrict__ x,
                               const float* __restrict__ w,
                               __nv_bfloat16* __restrict__ out) {
    int m = blockIdx.x;
    int tid = threadIdx.x;
    float4 v = reinterpret_cast<const float4*>(x + (size_t)m * DD)[tid];
    float ss = v.x * v.x + v.y * v.y + v.z * v.z + v.w * v.w;
    #pragma unroll
    for (int o = 16; o; o >>= 1) ss += __shfl_xor_sync(0xffffffffu, ss, o);
    __shared__ float red[4];
    if ((tid & 31) == 0) red[tid >> 5] = ss;
    __syncthreads();
    float tot = red[0] + red[1] + red[2] + red[3];
    float rs = rsqrtf(tot * (1.0f / DD) + 1e-5f);
    float4 wv = reinterpret_cast<const float4*>(w)[tid];
    __nv_bfloat162 p0 = __floats2bfloat162_rn(v.x * rs * wv.x, v.y * rs * wv.y);
    __nv_bfloat162 p1 = __floats2bfloat162_rn(v.z * rs * wv.z, v.w * rs * wv.w);
    uint2 o2 = make_uint2(*reinterpret_cast<uint32_t*>(&p0),
                          *reinterpret_cast<uint32_t*>(&p1));
    reinterpret_cast<uint2*>(out + (size_t)m * DD)[tid] = o2;
}

// ---------------- depthwise causal conv (K=4) + bias + silu (bf16 in/out) -------
__global__ void conv_silu_kernel(const __nv_bfloat16* __restrict__ xp,
                                 const float* __restrict__ w,
                                 const float* __restrict__ b,
                                 __nv_bfloat16* __restrict__ xc_bf) {
    int id = blockIdx.x * blockDim.x + threadIdx.x;
    if (id >= MM * EDIM) return;
    int e = id & (EDIM - 1);
    int mt = id >> 10;
    int t = mt & (LL - 1);
    float w0 = w[e*4+0], w1 = w[e*4+1], w2 = w[e*4+2], w3 = w[e*4+3];
    const __nv_bfloat16* base = xp + (size_t)mt * EDIM + e;
    float x0 = (t >= 3) ? __bfloat162float(base[-3 * EDIM]) : 0.f;
    float x1 = (t >= 2) ? __bfloat162float(base[-2 * EDIM]) : 0.f;
    float x2 = (t >= 1) ? __bfloat162float(base[-1 * EDIM]) : 0.f;
    float x3 = __bfloat162float(base[0]);
    float acc = b[e] + w0 * x0 + w1 * x1 + w2 * x2 + w3 * x3;
    acc = acc * (1.f / (1.f + __expf(-acc)));
    xc_bf[id] = __float2bfloat16(acc);
}

// ================= chunk-parallel selective scan =================================
// S1: per-chunk local scan from h=0; writes y_local, cumsum(delta), h_end.
#define SCAN_CH 64
#define S1_SMEM ((2 * SCAN_CH * 128 + SCAN_CH * 32) * (int)sizeof(float))

__global__ void scan_part1(const float* __restrict__ delta,
                           const __nv_bfloat16* __restrict__ xcb,
                           const float* __restrict__ dbc,
                           const float* __restrict__ A_log,
                           float* __restrict__ ypart,
                           float* __restrict__ csum,
                           float* __restrict__ hstate) {
    extern __shared__ float sh[];
    float* sD  = sh;                       // [64][128]
    float* sX  = sh + SCAN_CH * 128;
    float* sBC = sh + 2 * SCAN_CH * 128;   // [64][32]

    int b = blockIdx.y, c = blockIdx.z;
    int tid = threadIdx.x;
    int e0 = blockIdx.x * 128;
    int e = e0 + tid;

    float a[NSTATE];
    #pragma unroll
    for (int n = 0; n < NSTATE; n++) a[n] = -__expf(A_log[(size_t)e * NSTATE + n]);
    float a0 = a[0];
    bool pw = true;
    #pragma unroll
    for (int n = 0; n < NSTATE; n++)
        pw = pw && (fabsf(a[n] - a0 * (n + 1)) <= 1e-5f * fabsf(a[n]) + 1e-12f);

    float h[NSTATE];
    #pragma unroll
    for (int n = 0; n < NSTATE; n++) h[n] = 0.f;
    float cs = 0.f;

    const float* dbcb = dbc + (size_t)b * LL * 64;
    int tbase = c * CHLEN;

    for (int t0 = tbase; t0 < tbase + CHLEN; t0 += SCAN_CH) {
        __syncthreads();
        for (int i = tid; i < SCAN_CH * 32; i += 128) {
            int r = i >> 5, cc = i & 31;
            sBC[i] = dbcb[(size_t)(t0 + r) * 64 + 32 + cc];
        }
        for (int i = tid; i < SCAN_CH * 32; i += 128) {
            int r = i >> 5, c4 = i & 31;
            size_t m = (size_t)(b * LL + t0 + r);
            reinterpret_cast<float4*>(sD)[i] =
                *reinterpret_cast<const float4*>(delta + m * EDIM + e0 + c4 * 4);
        }
        for (int g = tid; g < SCAN_CH * 16; g += 128) {
            int r = g >> 4, c8 = g & 15;
            size_t m = (size_t)(b * LL + t0 + r);
            uint4 vx = *reinterpret_cast<const uint4*>(xcb + m * EDIM + e0 + c8 * 8);
            const __nv_bfloat162* px = reinterpret_cast<const __nv_bfloat162*>(&vx);
            int o = r * 128 + c8 * 8;
            #pragma unroll
            for (int k = 0; k < 4; k++) {
                float2 fx = __bfloat1622float2(px[k]);
                sX[o + 2*k] = fx.x; sX[o + 2*k + 1] = fx.y;
            }
        }
        __syncthreads();

        for (int i = 0; i < SCAN_CH; i++) {
            float d  = sD[i * 128 + tid];
            float xv = sX[i * 128 + tid];
            float du = d * xv;
            cs += d;
            float dA[NSTATE];
            if (pw) {
                float p = __expf(a0 * d);
                dA[0] = p;
                #pragma unroll
                for (int n = 1; n < NSTATE; n++) dA[n] = dA[n - 1] * p;
            } else {
                #pragma unroll
                for (int n = 0; n < NSTATE; n++) dA[n] = __expf(a[n] * d);
            }
            float yv = 0.f, yv2 = 0.f;
            const float* bc = sBC + i * 32;
            #pragma unroll
            for (int n = 0; n < NSTATE; n++) {
                h[n] = dA[n] * h[n] + du * bc[n];
                float cv = bc[16 + n];
                if (n & 1) yv2 += h[n] * cv; else yv += h[n] * cv;
            }
            size_t idx = (size_t)(b * LL + t0 + i) * EDIM + e;
            ypart[idx] = yv + yv2;
            csum[idx] = cs;
        }
    }

    // h_end -> hstate[b][c][e][16] (float4 x4)
    float* hp = hstate + ((size_t)(b * NCHUNK + c) * EDIM + e) * NSTATE;
    #pragma unroll
    for (int q = 0; q < 4; q++)
        reinterpret_cast<float4*>(hp)[q] =
            make_float4(h[q*4+0], h[q*4+1], h[q*4+2], h[q*4+3]);
}

// S2: sequential combine across chunks; hstate becomes h_in (state at chunk entry).
__global__ void scan_combine(const float* __restrict__ csum,
                             const float* __restrict__ A_log,
                             float* __restrict__ hstate,
                             float* __restrict__ meta) {
    int id = blockIdx.x * blockDim.x + threadIdx.x;   // b*EDIM + e
    if (id >= BB * EDIM) return;
    int b = id >> 10, e = id & (EDIM - 1);

    float a[NSTATE];
    #pragma unroll
    for (int n = 0; n < NSTATE; n++) a[n] = -__expf(A_log[(size_t)e * NSTATE + n]);
    float a0 = a[0];
    bool pw = true;
    #pragma unroll
    for (int n = 0; n < NSTATE; n++)
        pw = pw && (fabsf(a[n] - a0 * (n + 1)) <= 1e-5f * fabsf(a[n]) + 1e-12f);
    if (b == 0) { meta[e * 2] = a0; meta[e * 2 + 1] = pw ? 1.f : 0.f; }

    float carry[NSTATE];
    #pragma unroll
    for (int n = 0; n < NSTATE; n++) carry[n] = 0.f;

    for (int c = 0; c < NCHUNK; c++) {
        float SE = csum[(size_t)(b * LL + c * CHLEN + CHLEN - 1) * EDIM + e];
        float f[NSTATE];
        if (pw) {
            float p = __expf(a0 * SE);
            f[0] = p;
            #pragma unroll
            for (int n = 1; n < NSTATE; n++) f[n] = f[n - 1] * p;
        } else {
            #pragma unroll
            for (int n = 0; n < NSTATE; n++) f[n] = __expf(a[n] * SE);
        }
        float* hp = hstate + ((size_t)(b * NCHUNK + c) * EDIM + e) * NSTATE;
        #pragma unroll
        for (int q = 0; q < 4; q++) {
            float4 he = reinterpret_cast<float4*>(hp)[q];
            reinterpret_cast<float4*>(hp)[q] =
                make_float4(carry[q*4+0], carry[q*4+1], carry[q*4+2], carry[q*4+3]);
            carry[q*4+0] = f[q*4+0] * carry[q*4+0] + he.x;
            carry[q*4+1] = f[q*4+1] * carry[q*4+1] + he.y;
            carry[q*4+2] = f[q*4+2] * carry[q*4+2] + he.z;
            carry[q*4+3] = f[q*4+3] * carry[q*4+3] + he.w;
        }
    }
}

// S3: fully parallel correction + D + gating -> bf16 y.
__global__ void scan_part2(const float* __restrict__ ypart,
                           const float* __restrict__ csum,
                           const float* __restrict__ dbc,
                           const __nv_bfloat16* __restrict__ xcb,
                           const __nv_bfloat16* __restrict__ zb,
                           const float* __restrict__ A_log,
                           const float* __restrict__ Dp,
                           const float* __restrict__ hstate,
                           const float* __restrict__ meta,
                           __nv_bfloat16* __restrict__ y) {
    __shared__ float sC[NSTATE];
    size_t id = (size_t)blockIdx.x * 256 + threadIdx.x;
    int e = (int)(id & (EDIM - 1));
    size_t m = id >> 10;
    int b = (int)(m >> 11);
    int t = (int)(m & (LL - 1));
    int c = t >> 7;

    if (threadIdx.x < NSTATE) sC[threadIdx.x] = dbc[m * 64 + 48 + threadIdx.x];
    __syncthreads();

    float S = csum[id];
    float a0 = meta[e * 2];
    bool pw = meta[e * 2 + 1] > 0.5f;
    float f[NSTATE];
    if (pw) {
        float p = __expf(a0 * S);
        f[0] = p;
        #pragma unroll
        for (int n = 1; n < NSTATE; n++) f[n] = f[n - 1] * p;
    } else {
        #pragma unroll
        for (int n = 0; n < NSTATE; n++)
            f[n] = __expf(-__expf(A_log[(size_t)e * NSTATE + n]) * S);
    }

    const float* hp = hstate + ((size_t)(b * NCHUNK + c) * EDIM + e) * NSTATE;
    float corr = 0.f, corr2 = 0.f;
    #pragma unroll
    for (int q = 0; q < 4; q++) {
        float4 hv = reinterpret_cast<const float4*>(hp)[q];
        corr  += sC[q*4+0] * f[q*4+0] * hv.x + sC[q*4+2] * f[q*4+2] * hv.z;
        corr2 += sC[q*4+1] * f[q*4+1] * hv.y + sC[q*4+3] * f[q*4+3] * hv.w;
    }
    float yv = ypart[id] + corr + corr2;
    float xv = __bfloat162float(xcb[id]);
    float zv = __bfloat162float(zb[id]);
    float sz = zv * (1.f / (1.f + __expf(-zv)));
    y[id] = __float2bfloat16((yv + Dp[e] * xv) * sz);
}

// ---------------- misc -----------------------------------------------------------
__global__ void init_x(const float* __restrict__ x, const int* __restrict__ mask,
                       float* __restrict__ xb) {
    int id = blockIdx.x * blockDim.x + threadIdx.x;
    if (id < MM * DD) xb[id] = x[id] * (float)mask[id >> 9];
}

__global__ void cvt_bf16(const float* __restrict__ src, __nv_bfloat16* __restrict__ dst, int n) {
    int id = blockIdx.x * blockDim.x + threadIdx.x;
    if (id < n) dst[id] = __float2bfloat16(src[id]);
}

__global__ void tail_kernel(const float* __restrict__ xb, float* __restrict__ out) {
    int id = blockIdx.x * blockDim.x + threadIdx.x;
    if (id < BB * DD) {
        int b = id / DD, d = id % DD;
        out[id] = xb[(size_t)b * LL * DD + d];
    }
}

// ---------------- launch ---------------------------------------------------------
extern "C" void kernel_launch(void* const* d_in, const int* in_sizes, int n_in,
                              void* d_out, int out_size) {
    const float* x        = (const float*)d_in[0];
    const int*   mask     = (const int*)d_in[1];
    const float* norm_w   = (const float*)d_in[2];
    const float* in_w     = (const float*)d_in[3];
    const float* conv_w   = (const float*)d_in[4];
    const float* conv_b   = (const float*)d_in[5];
    const float* xproj_w  = (const float*)d_in[6];
    const float* dtproj_w = (const float*)d_in[7];
    const float* dtproj_b = (const float*)d_in[8];
    const float* A_log    = (const float*)d_in[9];
    const float* D_param  = (const float*)d_in[10];
    const float* out_w    = (const float*)d_in[11];

    float* xb   = (float*)d_out;
    float* tail = xb + (size_t)MM * DD;

    float *dbcp, *deltap, *ypartp, *csump, *hstatep, *metap;
    __nv_bfloat16 *ubf, *xpbf, *zbf, *xcbf, *ybf, *inwbf, *outwbf, *xprojwbf;
    cudaGetSymbolAddress((void**)&dbcp, g_dbc);
    cudaGetSymbolAddress((void**)&deltap, g_delta);
    cudaGetSymbolAddress((void**)&ypartp, g_ypart);
    cudaGetSymbolAddress((void**)&csump, g_csum);
    cudaGetSymbolAddress((void**)&hstatep, g_hstate);
    cudaGetSymbolAddress((void**)&metap, g_meta);
    cudaGetSymbolAddress((void**)&ubf, g_u_bf);
    cudaGetSymbolAddress((void**)&xpbf, g_xp_bf);
    cudaGetSymbolAddress((void**)&zbf, g_z_bf);
    cudaGetSymbolAddress((void**)&xcbf, g_xc_bf);
    cudaGetSymbolAddress((void**)&ybf, g_y_bf);
    cudaGetSymbolAddress((void**)&inwbf, g_inw_bf);
    cudaGetSymbolAddress((void**)&outwbf, g_outw_bf);
    cudaGetSymbolAddress((void**)&xprojwbf, g_xprojw_bf);

    cudaFuncSetAttribute(scan_part1,
                         cudaFuncAttributeMaxDynamicSharedMemorySize, S1_SMEM);
    constexpr int SM128 = 3 * (128 * 128 + 128 * 128);   // 96 KB
    constexpr int SM64  = 3 * (128 * 128 + 64 * 128);    // 72 KB
    cudaFuncSetAttribute(mma_gemm<128, 1>,
                         cudaFuncAttributeMaxDynamicSharedMemorySize, SM128);
    cudaFuncSetAttribute(mma_gemm<128, 2>,
                         cudaFuncAttributeMaxDynamicSharedMemorySize, SM128);
    cudaFuncSetAttribute(mma_gemm<64, 0>,
                         cudaFuncAttributeMaxDynamicSharedMemorySize, SM64);

    // weight conversions (once per call)
    {
        int n1 = NLAY * 2 * EDIM * DD;
        cvt_bf16<<<(n1 + 255) / 256, 256>>>(in_w, inwbf, n1);
        int n2 = NLAY * DD * EDIM;
        cvt_bf16<<<(n2 + 255) / 256, 256>>>(out_w, outwbf, n2);
        int n3 = NLAY * 64 * EDIM;
        cvt_bf16<<<(n3 + 255) / 256, 256>>>(xproj_w, xprojwbf, n3);
    }

    init_x<<<(MM * DD + 255) / 256, 256>>>(x, mask, xb);

    for (int l = 0; l < NLAY; l++) {
        rmsnorm_kernel<<<MM, 128>>>(xb, norm_w + l * DD, ubf);

        // xz = u @ in_w^T : M=8192, N=2048, K=512 -> split bf16 xp/z
        mma_gemm<128, 1><<<dim3(2 * EDIM / 128, MM / 128), 256, SM128>>>(
            ubf, inwbf + (size_t)l * 2 * EDIM * DD, nullptr, xpbf, zbf,
            MM, 2 * EDIM, DD, 0, nullptr);

        conv_silu_kernel<<<(MM * EDIM + 255) / 256, 256>>>(
            xpbf, conv_w + (size_t)l * EDIM * KCONV, conv_b + l * EDIM, xcbf);

        // dbc = xc @ xproj_w^T : M=8192, N=64, K=1024 (fp32 out)
        mma_gemm<64, 0><<<dim3(1, MM / 128), 256, SM64>>>(
            xcbf, xprojwbf + (size_t)l * 64 * EDIM, dbcp, nullptr, nullptr,
            MM, 64, EDIM, 64, nullptr);

        // delta = softplus(dt @ dtproj_w^T + b) : K=32, fp32 path
        gemm_softplus<128,128,16,8,8><<<dim3(EDIM / 128, MM / 128), 256>>>(
            dbcp, dtproj_w + (size_t)l * EDIM * RRANK, deltap,
            MM, EDIM, RRANK, 64, RRANK, EDIM, dtproj_b + l * EDIM);

        // chunk-parallel scan
        scan_part1<<<dim3(EDIM / 128, BB, NCHUNK), 128, S1_SMEM>>>(
            deltap, xcbf, dbcp, A_log + (size_t)l * EDIM * NSTATE,
            ypartp, csump, hstatep);
        scan_combine<<<(BB * EDIM + 255) / 256, 256>>>(
            csump, A_log + (size_t)l * EDIM * NSTATE, hstatep, metap);
        scan_part2<<<(int)(((size_t)MM * EDIM) / 256), 256>>>(
            ypartp, csump, dbcp, xcbf, zbf,
            A_log + (size_t)l * EDIM * NSTATE, D_param + l * EDIM,
            hstatep, metap, ybf);

        // x = (x + y @ out_w^T) * mask : M=8192, N=512, K=1024
        mma_gemm<128, 2><<<dim3(DD / 128, MM / 128), 256, SM128>>>(
            ybf, outwbf + (size_t)l * DD * EDIM, xb, nullptr, nullptr,
            MM, DD, EDIM, DD, mask);
    }

    tail_kernel<<<(BB * DD + 255) / 256, 256>>>(xb, tail);
}

// round 16
// speedup vs baseline: 3.9347x; 1.1790x over previous
#include <cuda_runtime.h>
#include <cuda_bf16.h>
#include <cstdint>

#define BB 4
#define LL 2048
#define DD 512
#define NLAY 2
#define EDIM 1024
#define NSTATE 16
#define RRANK 32
#define KCONV 4
#define MM (BB*LL)   // 8192 tokens
#define NCHUNK 16
#define CHLEN 128    // LL / NCHUNK

// ---------------- scratch (static device allocations) ---------------------------
__device__ float g_dbc[(size_t)MM * 64];            // x-proj output (dt|B|C) fp32
__device__ float g_ypart[(size_t)MM * EDIM];        // local scan output fp32
__device__ float g_csum[(size_t)MM * EDIM];         // within-chunk cumsum(delta)
__device__ float g_hstate[(size_t)BB * NCHUNK * EDIM * NSTATE]; // h_end -> h_in
__device__ float g_meta[EDIM * 2];                  // {a0, pw} per channel
__device__ __nv_bfloat16 g_u_bf[(size_t)MM * DD];       // normed input
__device__ __nv_bfloat16 g_xp_bf[(size_t)MM * EDIM];    // in-proj x half
__device__ __nv_bfloat16 g_z_bf[(size_t)MM * EDIM];     // in-proj z half
__device__ __nv_bfloat16 g_xc_bf[(size_t)MM * EDIM];    // conv+silu output
__device__ __nv_bfloat16 g_y_bf[(size_t)MM * EDIM];     // scan output
__device__ __nv_bfloat16 g_inw_bf[(size_t)NLAY * 2 * EDIM * DD];
__device__ __nv_bfloat16 g_outw_bf[(size_t)NLAY * DD * EDIM];
__device__ __nv_bfloat16 g_xprojw_bf[(size_t)NLAY * 64 * EDIM];

// ================= helpers ======================================================
__device__ __forceinline__ uint32_t smem_u32(const void* p) {
    uint32_t a;
    asm("{ .reg .u64 t; cvta.to.shared.u64 t, %1; cvt.u32.u64 %0, t; }"
        : "=r"(a) : "l"(p));
    return a;
}
#define SWZ(o) ((o) ^ (((o) >> 3) & 0x70))

__device__ __forceinline__ void cp16(uint32_t dst, const void* src) {
    asm volatile("cp.async.cg.shared.global [%0], [%1], 16;" :: "r"(dst), "l"(src));
}
__device__ __forceinline__ void cp_commit() {
    asm volatile("cp.async.commit_group;");
}
template<int N>
__device__ __forceinline__ void cp_wait() {
    asm volatile("cp.async.wait_group %0;" :: "n"(N));
}

__device__ __forceinline__ void ldsm_x4(uint32_t& r0, uint32_t& r1,
                                        uint32_t& r2, uint32_t& r3, uint32_t addr) {
    asm volatile("ldmatrix.sync.aligned.m8n8.x4.shared.b16 {%0,%1,%2,%3}, [%4];"
                 : "=r"(r0), "=r"(r1), "=r"(r2), "=r"(r3) : "r"(addr));
}
__device__ __forceinline__ void mma16816(float* d, const uint32_t* a, const uint32_t* b) {
    asm volatile("mma.sync.aligned.m16n8k16.row.col.f32.bf16.bf16.f32 "
                 "{%0,%1,%2,%3}, {%4,%5,%6,%7}, {%8,%9}, {%0,%1,%2,%3};"
                 : "+f"(d[0]), "+f"(d[1]), "+f"(d[2]), "+f"(d[3])
                 : "r"(a[0]), "r"(a[1]), "r"(a[2]), "r"(a[3]),
                   "r"(b[0]), "r"(b[1]));
}

// ================= bf16 HMMA GEMM: C[M,N] = A[M,K] @ B[N,K]^T ===================
// 3-stage cp.async pipeline; prefetch after the barrier (slot provably free).
// EPI 0: fp32 C store.
// EPI 1: split bf16 store: n<EDIM -> xp_bf, else -> z_bf (both [M][EDIM]).
// EPI 2: C = (C + acc) * mask[m]; rows with (m % LL)==0 also copied to tail.
template<int BN, int EPI>
__global__ __launch_bounds__(256, 2)
void mma_gemm(const __nv_bfloat16* __restrict__ A, const __nv_bfloat16* __restrict__ Bw,
              float* __restrict__ C,
              __nv_bfloat16* __restrict__ xp_bf, __nv_bfloat16* __restrict__ z_bf,
              int M, int N, int K, int ldc, const int* __restrict__ mask,
              float* __restrict__ tail) {
    constexpr int BM = 128, BK = 64;
    constexpr int NW = 4, MW = 2;
    constexpr int WM = BM / MW;              // 64
    constexpr int WN = BN / NW;              // 32 or 16
    constexpr int MFRAG = WM / 16;           // 4
    constexpr int NFRAG = WN / 8;            // 4 or 2
    constexpr int ASZ = BM * 128;
    constexpr int BSZ = BN * 128;
    constexpr int STG = 3;

    extern __shared__ __align__(1024) char dynsmem[];
    char* sA = dynsmem;
    char* sB = dynsmem + STG * ASZ;

    int tid = threadIdx.x;
    int wid = tid >> 5, lane = tid & 31;
    int bm = blockIdx.y * BM, bn = blockIdx.x * BN;
    int wm = (wid / NW) * WM;
    int wn = (wid % NW) * WN;
    uint32_t sAb = smem_u32(sA), sBb = smem_u32(sB);

    uint32_t aBase[MFRAG];
    #pragma unroll
    for (int i = 0; i < MFRAG; i++)
        aBase[i] = (uint32_t)((wm + i * 16 + (lane & 15)) * 128 + (lane >> 4) * 16);
    uint32_t bBase[NFRAG / 2];
    #pragma unroll
    for (int j = 0; j < NFRAG / 2; j++)
        bBase[j] = (uint32_t)((wn + j * 16 + (lane & 7) + ((lane >> 4) & 1) * 8) * 128
                              + ((lane >> 3) & 1) * 16);

    float acc[MFRAG][NFRAG][4];
    #pragma unroll
    for (int i = 0; i < MFRAG; i++)
        #pragma unroll
        for (int j = 0; j < NFRAG; j++)
            #pragma unroll
            for (int q = 0; q < 4; q++) acc[i][j][q] = 0.f;

    const int nk = K / BK;

#define LOAD_STAGE(kc, st) do {                                                 \
        _Pragma("unroll")                                                       \
        for (int i = 0; i < (BM * 8) / 256; i++) {                              \
            int idx = tid + i * 256;                                            \
            int r = idx >> 3, c8 = idx & 7;                                     \
            cp16(sAb + (st) * ASZ + SWZ((uint32_t)(r * 128 + c8 * 16)),         \
                 A + (size_t)(bm + r) * K + (kc) * 64 + c8 * 8);                \
        }                                                                       \
        _Pragma("unroll")                                                       \
        for (int i = 0; i < (BN * 8) / 256; i++) {                              \
            int idx = tid + i * 256;                                            \
            int r = idx >> 3, c8 = idx & 7;                                     \
            cp16(sBb + (st) * BSZ + SWZ((uint32_t)(r * 128 + c8 * 16)),         \
                 Bw + (size_t)(bn + r) * K + (kc) * 64 + c8 * 8);               \
        }                                                                       \
    } while (0)

    LOAD_STAGE(0, 0); cp_commit();
    LOAD_STAGE(1, 1); cp_commit();

    int st = 0;
    for (int kc = 0; kc < nk; kc++) {
        cp_wait<1>();
        __syncthreads();
        if (kc + 2 < nk) {
            int st2 = st + 2 >= STG ? st + 2 - STG : st + 2;
            LOAD_STAGE(kc + 2, st2);
        }
        cp_commit();

        uint32_t aS = sAb + st * ASZ, bS = sBb + st * BSZ;
        #pragma unroll
        for (int ks = 0; ks < 4; ks++) {
            uint32_t af[MFRAG][4];
            #pragma unroll
            for (int i = 0; i < MFRAG; i++)
                ldsm_x4(af[i][0], af[i][1], af[i][2], af[i][3],
                        aS + SWZ(aBase[i] + ks * 32));
            uint32_t bf[NFRAG][2];
            #pragma unroll
            for (int j = 0; j < NFRAG / 2; j++) {
                uint32_t r0, r1, r2, r3;
                ldsm_x4(r0, r1, r2, r3, bS + SWZ(bBase[j] + ks * 32));
                bf[j * 2][0] = r0; bf[j * 2][1] = r1;
                bf[j * 2 + 1][0] = r2; bf[j * 2 + 1][1] = r3;
            }
            #pragma unroll
            for (int i = 0; i < MFRAG; i++)
                #pragma unroll
                for (int j = 0; j < NFRAG; j++)
                    mma16816(acc[i][j], af[i], bf[j]);
        }
        st = (st + 1 == STG) ? 0 : st + 1;
    }
#undef LOAD_STAGE

    // ---- epilogue ----
    bool isz = false;
    __nv_bfloat16* OB = nullptr;
    if (EPI == 1) { isz = (bn >= EDIM); OB = isz ? z_bf : xp_bf; }
    #pragma unroll
    for (int i = 0; i < MFRAG; i++) {
        int r0 = bm + wm + i * 16 + (lane >> 2);
        int r1 = r0 + 8;
        float mk0 = 1.f, mk1 = 1.f;
        if (EPI == 2) { mk0 = (float)mask[r0]; mk1 = (float)mask[r1]; }
        #pragma unroll
        for (int j = 0; j < NFRAG; j++) {
            int c = bn + wn + j * 8 + (lane & 3) * 2;
            if (EPI == 1) {
                int cb = c - (isz ? EDIM : 0);
                __nv_bfloat162 b0 = __floats2bfloat162_rn(acc[i][j][0], acc[i][j][1]);
                __nv_bfloat162 b1 = __floats2bfloat162_rn(acc[i][j][2], acc[i][j][3]);
                *reinterpret_cast<__nv_bfloat162*>(OB + (size_t)r0 * EDIM + cb) = b0;
                *reinterpret_cast<__nv_bfloat162*>(OB + (size_t)r1 * EDIM + cb) = b1;
            } else {
                size_t i0 = (size_t)r0 * ldc + c;
                size_t i1 = (size_t)r1 * ldc + c;
                float2 v0 = make_float2(acc[i][j][0], acc[i][j][1]);
                float2 v1 = make_float2(acc[i][j][2], acc[i][j][3]);
                if (EPI == 2) {
                    float2 o0 = *reinterpret_cast<float2*>(C + i0);
                    float2 o1 = *reinterpret_cast<float2*>(C + i1);
                    v0 = make_float2((o0.x + v0.x) * mk0, (o0.y + v0.y) * mk0);
                    v1 = make_float2((o1.x + v1.x) * mk1, (o1.y + v1.y) * mk1);
                }
                *reinterpret_cast<float2*>(C + i0) = v0;
                *reinterpret_cast<float2*>(C + i1) = v1;
                if (EPI == 2 && tail != nullptr && (r0 & (LL - 1)) == 0) {
                    int bidx = r0 >> 11;   // r0 / LL
                    *reinterpret_cast<float2*>(tail + (size_t)bidx * DD + c) = v0;
                }
            }
        }
    }
}

// ---------------- rmsnorm -> bf16 ------------------------------------------------
__global__ void rmsnorm_kernel(const float* __restrict__ x,
                               const float* __restrict__ w,
                               __nv_bfloat16* __restrict__ out) {
    int m = blockIdx.x;
    int tid = threadIdx.x;
    float4 v = reinterpret_cast<const float4*>(x + (size_t)m * DD)[tid];
    float ss = v.x * v.x + v.y * v.y + v.z * v.z + v.w * v.w;
    #pragma unroll
    for (int o = 16; o; o >>= 1) ss += __shfl_xor_sync(0xffffffffu, ss, o);
    __shared__ float red[4];
    if ((tid & 31) == 0) red[tid >> 5] = ss;
    __syncthreads();
    float tot = red[0] + red[1] + red[2] + red[3];
    float rs = rsqrtf(tot * (1.0f / DD) + 1e-5f);
    float4 wv = reinterpret_cast<const float4*>(w)[tid];
    __nv_bfloat162 p0 = __floats2bfloat162_rn(v.x * rs * wv.x, v.y * rs * wv.y);
    __nv_bfloat162 p1 = __floats2bfloat162_rn(v.z * rs * wv.z, v.w * rs * wv.w);
    uint2 o2 = make_uint2(*reinterpret_cast<uint32_t*>(&p0),
                          *reinterpret_cast<uint32_t*>(&p1));
    reinterpret_cast<uint2*>(out + (size_t)m * DD)[tid] = o2;
}

// ---------------- depthwise causal conv (K=4) + bias + silu (bf16 in/out) -------
__global__ void conv_silu_kernel(const __nv_bfloat16* __restrict__ xp,
                                 const float* __restrict__ w,
                                 const float* __restrict__ b,
                                 __nv_bfloat16* __restrict__ xc_bf) {
    int id = blockIdx.x * blockDim.x + threadIdx.x;
    if (id >= MM * EDIM) return;
    int e = id & (EDIM - 1);
    int mt = id >> 10;
    int t = mt & (LL - 1);
    float w0 = w[e*4+0], w1 = w[e*4+1], w2 = w[e*4+2], w3 = w[e*4+3];
    const __nv_bfloat16* base = xp + (size_t)mt * EDIM + e;
    float x0 = (t >= 3) ? __bfloat162float(base[-3 * EDIM]) : 0.f;
    float x1 = (t >= 2) ? __bfloat162float(base[-2 * EDIM]) : 0.f;
    float x2 = (t >= 1) ? __bfloat162float(base[-1 * EDIM]) : 0.f;
    float x3 = __bfloat162float(base[0]);
    float acc = b[e] + w0 * x0 + w1 * x1 + w2 * x2 + w3 * x3;
    acc = acc * (1.f / (1.f + __expf(-acc)));
    xc_bf[id] = __float2bfloat16(acc);
}

// ================= chunk-parallel selective scan =================================
// S1: per-chunk local scan from h=0, with delta = softplus(dt@W^T + b) computed
// inline (dt = dbc cols 0:32, already staged). Writes y_local, cumsum, h_end.
#define SCAN_CH 64
#define S1_SMEM ((SCAN_CH * 128 + SCAN_CH * 64) * (int)sizeof(float))   // 48 KB

__global__ void scan_part1(const __nv_bfloat16* __restrict__ xcb,
                           const float* __restrict__ dbc,
                           const float* __restrict__ A_log,
                           const float* __restrict__ dtw,   // [EDIM][32]
                           const float* __restrict__ dtb,   // [EDIM]
                           float* __restrict__ ypart,
                           float* __restrict__ csum,
                           float* __restrict__ hstate) {
    extern __shared__ float sh[];
    float* sX   = sh;                      // [64][128]
    float* sDBC = sh + SCAN_CH * 128;      // [64][64]  (dt | B | C)

    int b = blockIdx.y, c = blockIdx.z;
    int tid = threadIdx.x;
    int e0 = blockIdx.x * 128;
    int e = e0 + tid;

    float a[NSTATE];
    #pragma unroll
    for (int n = 0; n < NSTATE; n++) a[n] = -__expf(A_log[(size_t)e * NSTATE + n]);
    float a0 = a[0];
    bool pw = true;
    #pragma unroll
    for (int n = 0; n < NSTATE; n++)
        pw = pw && (fabsf(a[n] - a0 * (n + 1)) <= 1e-5f * fabsf(a[n]) + 1e-12f);

    // dt projection row for this channel: 32 floats in registers
    float4 w4[8];
    #pragma unroll
    for (int q = 0; q < 8; q++)
        w4[q] = reinterpret_cast<const float4*>(dtw + (size_t)e * RRANK)[q];
    float bias = dtb[e];

    float h[NSTATE];
    #pragma unroll
    for (int n = 0; n < NSTATE; n++) h[n] = 0.f;
    float cs = 0.f;

    const float* dbcb = dbc + (size_t)b * LL * 64;
    int tbase = c * CHLEN;

    for (int t0 = tbase; t0 < tbase + CHLEN; t0 += SCAN_CH) {
        __syncthreads();
        // stage full dbc rows (64 floats each) as float4
        for (int i = tid; i < SCAN_CH * 16; i += 128) {
            int r = i >> 4, c4 = i & 15;
            reinterpret_cast<float4*>(sDBC)[i] =
                reinterpret_cast<const float4*>(dbcb + (size_t)(t0 + r) * 64)[c4];
        }
        for (int g = tid; g < SCAN_CH * 16; g += 128) {
            int r = g >> 4, c8 = g & 15;
            size_t m = (size_t)(b * LL + t0 + r);
            uint4 vx = *reinterpret_cast<const uint4*>(xcb + m * EDIM + e0 + c8 * 8);
            const __nv_bfloat162* px = reinterpret_cast<const __nv_bfloat162*>(&vx);
            int o = r * 128 + c8 * 8;
            #pragma unroll
            for (int k = 0; k < 4; k++) {
                float2 fx = __bfloat1622float2(px[k]);
                sX[o + 2*k] = fx.x; sX[o + 2*k + 1] = fx.y;
            }
        }
        __syncthreads();

        for (int i = 0; i < SCAN_CH; i++) {
            const float* row = sDBC + i * 64;
            // delta = softplus(dot(dt, w) + bias)  (8x LDS.128 broadcast)
            float s = bias;
            #pragma unroll
            for (int q = 0; q < 8; q++) {
                float4 dt4 = reinterpret_cast<const float4*>(row)[q];
                s += w4[q].x * dt4.x + w4[q].y * dt4.y
                   + w4[q].z * dt4.z + w4[q].w * dt4.w;
            }
            float d = (s > 20.f) ? s : log1pf(__expf(s));
            float xv = sX[i * 128 + tid];
            float du = d * xv;
            cs += d;
            float dA[NSTATE];
            if (pw) {
                float p = __expf(a0 * d);
                dA[0] = p;
                #pragma unroll
                for (int n = 1; n < NSTATE; n++) dA[n] = dA[n - 1] * p;
            } else {
                #pragma unroll
                for (int n = 0; n < NSTATE; n++) dA[n] = __expf(a[n] * d);
            }
            float yv = 0.f, yv2 = 0.f;
            const float* bc = row + 32;
            #pragma unroll
            for (int n = 0; n < NSTATE; n++) {
                h[n] = dA[n] * h[n] + du * bc[n];
                float cv = bc[16 + n];
                if (n & 1) yv2 += h[n] * cv; else yv += h[n] * cv;
            }
            size_t idx = (size_t)(b * LL + t0 + i) * EDIM + e;
            ypart[idx] = yv + yv2;
            csum[idx] = cs;
        }
    }

    float* hp = hstate + ((size_t)(b * NCHUNK + c) * EDIM + e) * NSTATE;
    #pragma unroll
    for (int q = 0; q < 4; q++)
        reinterpret_cast<float4*>(hp)[q] =
            make_float4(h[q*4+0], h[q*4+1], h[q*4+2], h[q*4+3]);
}

// S2: sequential combine across chunks; hstate becomes h_in (state at chunk entry).
__global__ void scan_combine(const float* __restrict__ csum,
                             const float* __restrict__ A_log,
                             float* __restrict__ hstate,
                             float* __restrict__ meta) {
    int id = blockIdx.x * blockDim.x + threadIdx.x;   // b*EDIM + e
    if (id >= BB * EDIM) return;
    int b = id >> 10, e = id & (EDIM - 1);

    float a[NSTATE];
    #pragma unroll
    for (int n = 0; n < NSTATE; n++) a[n] = -__expf(A_log[(size_t)e * NSTATE + n]);
    float a0 = a[0];
    bool pw = true;
    #pragma unroll
    for (int n = 0; n < NSTATE; n++)
        pw = pw && (fabsf(a[n] - a0 * (n + 1)) <= 1e-5f * fabsf(a[n]) + 1e-12f);
    if (b == 0) { meta[e * 2] = a0; meta[e * 2 + 1] = pw ? 1.f : 0.f; }

    float carry[NSTATE];
    #pragma unroll
    for (int n = 0; n < NSTATE; n++) carry[n] = 0.f;

    for (int c = 0; c < NCHUNK; c++) {
        float SE = csum[(size_t)(b * LL + c * CHLEN + CHLEN - 1) * EDIM + e];
        float f[NSTATE];
        if (pw) {
            float p = __expf(a0 * SE);
            f[0] = p;
            #pragma unroll
            for (int n = 1; n < NSTATE; n++) f[n] = f[n - 1] * p;
        } else {
            #pragma unroll
            for (int n = 0; n < NSTATE; n++) f[n] = __expf(a[n] * SE);
        }
        float* hp = hstate + ((size_t)(b * NCHUNK + c) * EDIM + e) * NSTATE;
        #pragma unroll
        for (int q = 0; q < 4; q++) {
            float4 he = reinterpret_cast<float4*>(hp)[q];
            reinterpret_cast<float4*>(hp)[q] =
                make_float4(carry[q*4+0], carry[q*4+1], carry[q*4+2], carry[q*4+3]);
            carry[q*4+0] = f[q*4+0] * carry[q*4+0] + he.x;
            carry[q*4+1] = f[q*4+1] * carry[q*4+1] + he.y;
            carry[q*4+2] = f[q*4+2] * carry[q*4+2] + he.z;
            carry[q*4+3] = f[q*4+3] * carry[q*4+3] + he.w;
        }
    }
}

// S3: fully parallel correction + D + gating -> bf16 y.
__global__ void scan_part2(const float* __restrict__ ypart,
                           const float* __restrict__ csum,
                           const float* __restrict__ dbc,
                           const __nv_bfloat16* __restrict__ xcb,
                           const __nv_bfloat16* __restrict__ zb,
                           const float* __restrict__ A_log,
                           const float* __restrict__ Dp,
                           const float* __restrict__ hstate,
                           const float* __restrict__ meta,
                           __nv_bfloat16* __restrict__ y) {
    __shared__ float sC[NSTATE];
    size_t id = (size_t)blockIdx.x * 256 + threadIdx.x;
    int e = (int)(id & (EDIM - 1));
    size_t m = id >> 10;
    int b = (int)(m >> 11);
    int t = (int)(m & (LL - 1));
    int c = t >> 7;

    if (threadIdx.x < NSTATE) sC[threadIdx.x] = dbc[m * 64 + 48 + threadIdx.x];
    __syncthreads();

    float S = csum[id];
    float a0 = meta[e * 2];
    bool pw = meta[e * 2 + 1] > 0.5f;
    float f[NSTATE];
    if (pw) {
        float p = __expf(a0 * S);
        f[0] = p;
        #pragma unroll
        for (int n = 1; n < NSTATE; n++) f[n] = f[n - 1] * p;
    } else {
        #pragma unroll
        for (int n = 0; n < NSTATE; n++)
            f[n] = __expf(-__expf(A_log[(size_t)e * NSTATE + n]) * S);
    }

    const float* hp = hstate + ((size_t)(b * NCHUNK + c) * EDIM + e) * NSTATE;
    float corr = 0.f, corr2 = 0.f;
    #pragma unroll
    for (int q = 0; q < 4; q++) {
        float4 hv = reinterpret_cast<const float4*>(hp)[q];
        corr  += sC[q*4+0] * f[q*4+0] * hv.x + sC[q*4+2] * f[q*4+2] * hv.z;
        corr2 += sC[q*4+1] * f[q*4+1] * hv.y + sC[q*4+3] * f[q*4+3] * hv.w;
    }
    float yv = ypart[id] + corr + corr2;
    float xv = __bfloat162float(xcb[id]);
    float zv = __bfloat162float(zb[id]);
    float sz = zv * (1.f / (1.f + __expf(-zv)));
    y[id] = __float2bfloat16((yv + Dp[e] * xv) * sz);
}

// ---------------- misc -----------------------------------------------------------
__global__ void init_x(const float* __restrict__ x, const int* __restrict__ mask,
                       float* __restrict__ xb) {
    int id = blockIdx.x * blockDim.x + threadIdx.x;
    if (id < MM * DD) xb[id] = x[id] * (float)mask[id >> 9];
}

// single-launch weight conversion (in_w | out_w | xproj_w)
__global__ void cvt_weights(const float* __restrict__ s1, int n1,
                            const float* __restrict__ s2, int n2,
                            const float* __restrict__ s3, int n3,
                            __nv_bfloat16* __restrict__ d1,
                            __nv_bfloat16* __restrict__ d2,
                            __nv_bfloat16* __restrict__ d3) {
    int id = blockIdx.x * blockDim.x + threadIdx.x;
    if (id < n1) d1[id] = __float2bfloat16(s1[id]);
    else if (id < n1 + n2) d2[id - n1] = __float2bfloat16(s2[id - n1]);
    else if (id < n1 + n2 + n3) d3[id - n1 - n2] = __float2bfloat16(s3[id - n1 - n2]);
}

// ---------------- launch ---------------------------------------------------------
extern "C" void kernel_launch(void* const* d_in, const int* in_sizes, int n_in,
                              void* d_out, int out_size) {
    const float* x        = (const float*)d_in[0];
    const int*   mask     = (const int*)d_in[1];
    const float* norm_w   = (const float*)d_in[2];
    const float* in_w     = (const float*)d_in[3];
    const float* conv_w   = (const float*)d_in[4];
    const float* conv_b   = (const float*)d_in[5];
    const float* xproj_w  = (const float*)d_in[6];
    const float* dtproj_w = (const float*)d_in[7];
    const float* dtproj_b = (const float*)d_in[8];
    const float* A_log    = (const float*)d_in[9];
    const float* D_param  = (const float*)d_in[10];
    const float* out_w    = (const float*)d_in[11];

    float* xb   = (float*)d_out;
    float* tail = xb + (size_t)MM * DD;

    float *dbcp, *ypartp, *csump, *hstatep, *metap;
    __nv_bfloat16 *ubf, *xpbf, *zbf, *xcbf, *ybf, *inwbf, *outwbf, *xprojwbf;
    cudaGetSymbolAddress((void**)&dbcp, g_dbc);
    cudaGetSymbolAddress((void**)&ypartp, g_ypart);
    cudaGetSymbolAddress((void**)&csump, g_csum);
    cudaGetSymbolAddress((void**)&hstatep, g_hstate);
    cudaGetSymbolAddress((void**)&metap, g_meta);
    cudaGetSymbolAddress((void**)&ubf, g_u_bf);
    cudaGetSymbolAddress((void**)&xpbf, g_xp_bf);
    cudaGetSymbolAddress((void**)&zbf, g_z_bf);
    cudaGetSymbolAddress((void**)&xcbf, g_xc_bf);
    cudaGetSymbolAddress((void**)&ybf, g_y_bf);
    cudaGetSymbolAddress((void**)&inwbf, g_inw_bf);
    cudaGetSymbolAddress((void**)&outwbf, g_outw_bf);
    cudaGetSymbolAddress((void**)&xprojwbf, g_xprojw_bf);

    cudaFuncSetAttribute(scan_part1,
                         cudaFuncAttributeMaxDynamicSharedMemorySize, S1_SMEM);
    constexpr int SM128 = 3 * (128 * 128 + 128 * 128);   // 96 KB
    constexpr int SM64  = 3 * (128 * 128 + 64 * 128);    // 72 KB
    cudaFuncSetAttribute(mma_gemm<128, 1>,
                         cudaFuncAttributeMaxDynamicSharedMemorySize, SM128);
    cudaFuncSetAttribute(mma_gemm<128, 2>,
                         cudaFuncAttributeMaxDynamicSharedMemorySize, SM128);
    cudaFuncSetAttribute(mma_gemm<64, 0>,
                         cudaFuncAttributeMaxDynamicSharedMemorySize, SM64);

    init_x<<<(MM * DD + 255) / 256, 256>>>(x, mask, xb);

    {
        int n1 = NLAY * 2 * EDIM * DD;
        int n2 = NLAY * DD * EDIM;
        int n3 = NLAY * 64 * EDIM;
        cvt_weights<<<(n1 + n2 + n3 + 255) / 256, 256>>>(
            in_w, n1, out_w, n2, xproj_w, n3, inwbf, outwbf, xprojwbf);
    }

    for (int l = 0; l < NLAY; l++) {
        rmsnorm_kernel<<<MM, 128>>>(xb, norm_w + l * DD, ubf);

        // xz = u @ in_w^T : M=8192, N=2048, K=512 -> split bf16 xp/z
        mma_gemm<128, 1><<<dim3(2 * EDIM / 128, MM / 128), 256, SM128>>>(
            ubf, inwbf + (size_t)l * 2 * EDIM * DD, nullptr, xpbf, zbf,
            MM, 2 * EDIM, DD, 0, nullptr, nullptr);

        conv_silu_kernel<<<(MM * EDIM + 255) / 256, 256>>>(
            xpbf, conv_w + (size_t)l * EDIM * KCONV, conv_b + l * EDIM, xcbf);

        // dbc = xc @ xproj_w^T : M=8192, N=64, K=1024 (fp32 out)
        mma_gemm<64, 0><<<dim3(1, MM / 128), 256, SM64>>>(
            xcbf, xprojwbf + (size_t)l * 64 * EDIM, dbcp, nullptr, nullptr,
            MM, 64, EDIM, 64, nullptr, nullptr);

        // chunk-parallel scan (delta computed inline in part1)
        scan_part1<<<dim3(EDIM / 128, BB, NCHUNK), 128, S1_SMEM>>>(
            xcbf, dbcp, A_log + (size_t)l * EDIM * NSTATE,
            dtproj_w + (size_t)l * EDIM * RRANK, dtproj_b + l * EDIM,
            ypartp, csump, hstatep);
        scan_combine<<<(BB * EDIM + 255) / 256, 256>>>(
            csump, A_log + (size_t)l * EDIM * NSTATE, hstatep, metap);
        scan_part2<<<(int)(((size_t)MM * EDIM) / 256), 256>>>(
            ypartp, csump, dbcp, xcbf, zbf,
            A_log + (size_t)l * EDIM * NSTATE, D_param + l * EDIM,
            hstatep, metap, ybf);

        // x = (x + y @ out_w^T) * mask ; last layer also writes tail rows
        mma_gemm<128, 2><<<dim3(DD / 128, MM / 128), 256, SM128>>>(
            ybf, outwbf + (size_t)l * DD * EDIM, xb, nullptr, nullptr,
            MM, DD, EDIM, DD, mask, (l == NLAY - 1) ? tail : nullptr);
    }
}